// round 7
// baseline (speedup 1.0000x reference)
#include <cuda_runtime.h>
#include <cuda_fp16.h>
#include <math.h>
#include <stdint.h>

#define BT   2048
#define TPH  32
#define EDIM 128
#define HDIM 256
#define GDIM 1024
#define VOC  256

#define MT 128
#define NT 128
#define GRID_M (BT / MT)     // 16
#define GRID_N (GDIM / NT)   // 8

// tiles: 128 rows x 64 k halfs, padded row stride 72 halfs (144 B)
#define TROW_B   144
#define TILE_B   (128 * TROW_B)          // 18432
#define BUF_B    (4 * TILE_B)            // Ah, Al, Bh, Bl = 73728
#define SM_C_OFF (2 * BUF_B)             // 147456
#define C_STRIDE 132
#define SM_TOTAL (SM_C_OFF + 128 * C_STRIDE * 4)   // 215040

// ---------------- device scratch ----------------
__device__ float   g_projP[2][VOC * GDIM];   // permuted proj tables (enc/dec)
__device__ __half  g_Ws[2][2][GDIM * HDIM];  // Whh fp16 splits (hi,lo), gate-interleaved rows
__device__ __half  g_hs[2][2][BT * HDIM];    // h fp16 splits, double buffered by parity
__device__ __half  g_eL[2][BT * HDIM];       // encoder-last h splits
__device__ float   g_c[BT * HDIM];
__device__ float   g_hf[BT * HDIM];          // fp32 h (decoder, for fc)
__device__ int     g_tok[BT];

// ---------------- fast pointwise (exp-based, ~1e-6 rel err) ----------------
__device__ __forceinline__ float fast_sigmoid(float x) {
    return __fdividef(1.f, 1.f + __expf(-x));
}
__device__ __forceinline__ float fast_tanh(float x) {
    return 1.f - __fdividef(2.f, __expf(2.f * x) + 1.f);
}

// ---------------- PTX helpers (portable: sm_80+) ----------------
__device__ __forceinline__ uint32_t smem_u32(const void* p) {
    uint32_t a;
    asm("{ .reg .u64 t; cvta.to.shared.u64 t, %1; cvt.u32.u64 %0, t; }" : "=r"(a) : "l"(p));
    return a;
}
__device__ __forceinline__ void cpa16(uint32_t saddr, const void* g) {
    asm volatile("cp.async.cg.shared.global [%0], [%1], 16;" :: "r"(saddr), "l"(g));
}
__device__ __forceinline__ void cpa_commit() {
    asm volatile("cp.async.commit_group;" ::: "memory");
}
template <int N>
__device__ __forceinline__ void cpa_wait() {
    asm volatile("cp.async.wait_group %0;" :: "n"(N) : "memory");
}
__device__ __forceinline__ void ldsm4(uint32_t* r, uint32_t addr) {
    asm volatile("ldmatrix.sync.aligned.m8n8.x4.shared.b16 {%0,%1,%2,%3}, [%4];"
        : "=r"(r[0]), "=r"(r[1]), "=r"(r[2]), "=r"(r[3]) : "r"(addr));
}
__device__ __forceinline__ void mma16816(float* c, const uint32_t* a,
                                         uint32_t b0, uint32_t b1) {
    asm volatile("mma.sync.aligned.m16n8k16.row.col.f32.f16.f16.f32 "
        "{%0,%1,%2,%3}, {%4,%5,%6,%7}, {%8,%9}, {%0,%1,%2,%3};"
        : "+f"(c[0]), "+f"(c[1]), "+f"(c[2]), "+f"(c[3])
        : "r"(a[0]), "r"(a[1]), "r"(a[2]), "r"(a[3]), "r"(b0), "r"(b1));
}

// ---------------- prep #1: split BOTH Whh into 2 fp16 planes, gate-interleaved
__global__ void split_w_kernel(const float* __restrict__ Wenc,
                               const float* __restrict__ Wdec)
{
    int gidx = blockIdx.x * blockDim.x + threadIdx.x;   // over 2*GDIM*HDIM
    if (gidx >= 2 * GDIM * HDIM) return;
    int which = gidx >= GDIM * HDIM;
    int idx = gidx - which * (GDIM * HDIM);
    const float* W = which ? Wdec : Wenc;
    int np = idx >> 8, k = idx & 255;
    int j = np >> 2, g = np & 3;                        // n' = j*4 + g
    float w = W[(size_t)(g * HDIM + j) * HDIM + k];
    __half hi = __float2half_rn(w);
    __half lo = __float2half_rn(w - __half2float(hi));
    g_Ws[which][0][idx] = hi;
    g_Ws[which][1][idx] = lo;
}

// ---------------- prep #2: permuted proj tables (both enc & dec) ------------
__global__ void proj_kernel(const float* __restrict__ emb,
                            const float* __restrict__ Wenc,
                            const float* __restrict__ b1e,
                            const float* __restrict__ b2e,
                            const float* __restrict__ Wdec,
                            const float* __restrict__ b1d,
                            const float* __restrict__ b2d)
{
    int which = blockIdx.z;
    const float* W  = which ? Wdec : Wenc;
    const float* b1 = which ? b1d : b1e;
    const float* b2 = which ? b2d : b2e;
    int v = blockIdx.x;
    __shared__ float es[EDIM];
    int tid = threadIdx.x;
    if (tid < EDIM) es[tid] = emb[v * EDIM + tid];
    __syncthreads();
    int n = blockIdx.y * 256 + tid;
    const float4* wr = (const float4*)(W + (size_t)n * EDIM);
    float acc = 0.f;
#pragma unroll
    for (int k4 = 0; k4 < EDIM / 4; k4++) {
        float4 w = wr[k4];
        acc += es[k4 * 4 + 0] * w.x + es[k4 * 4 + 1] * w.y
             + es[k4 * 4 + 2] * w.z + es[k4 * 4 + 3] * w.w;
    }
    int np = (n & 255) * 4 + (n >> 8);
    g_projP[which][(size_t)v * GDIM + np] = acc + b1[n] + b2[n];
}

// ---------------- init / dec-init ----------------
__global__ void init_kernel()
{
    int i = blockIdx.x * blockDim.x + threadIdx.x;
    if (i < BT * HDIM) {
        __half z = __float2half_rn(0.f);
        g_hs[0][0][i] = z; g_hs[0][1][i] = z;
        g_c[i] = 0.f;
    }
}
__global__ void dec_init_kernel(const int* __restrict__ sos)
{
    int i = blockIdx.x * blockDim.x + threadIdx.x;
    if (i < BT * HDIM) {
        g_hs[0][0][i] = g_eL[0][i];
        g_hs[0][1][i] = g_eL[1][i];
        g_c[i] = 0.f;
    }
    if (i < BT) g_tok[i] = sos[0];
}

// ---------------- stage loader: 4 tiles (Ah, Al, Bh, Bl), k-block kb ---------
__device__ __forceinline__ void load_stage(
    uint32_t sb, int buf, int kb,
    const __half* __restrict__ Ah, const __half* __restrict__ Al,
    const __half* __restrict__ Bh, const __half* __restrict__ Bl,
    int m0, int n0, int tid)
{
    const __half* srcs[4] = {Ah, Al, Bh, Bl};
    const uint32_t base = sb + buf * BUF_B;
    const int row = tid >> 1;
    const int c0 = (tid & 1) * 4;
#pragma unroll
    for (int tl = 0; tl < 4; tl++) {
        const int r0 = (tl < 2) ? m0 : n0;
        const __half* src = srcs[tl] + (size_t)(r0 + row) * HDIM + kb * 64 + c0 * 8;
        uint32_t dst = base + tl * TILE_B + row * TROW_B + c0 * 16;
#pragma unroll
        for (int c = 0; c < 4; c++)
            cpa16(dst + c * 16, src + c * 8);
    }
}

// ---------------- fused LSTM step: fp16-split mma.sync GEMM + pointwise -----
// C = Ah.Bh + Ah.Bl + Al.Bh ; 3 passes of 16 independent MMAs each.
__global__ __launch_bounds__(256, 1)
void lstm_step_mma(const int* __restrict__ phon, const int* __restrict__ lens,
                   int mode, int t)
{
    extern __shared__ char smem[];
    const uint32_t sb = smem_u32(smem);
    float* Cst = (float*)(smem + SM_C_OFF);

    const int tid  = threadIdx.x;
    const int lane = tid & 31;
    const int wid  = tid >> 5;
    const int wm = wid & 1, wn = wid >> 1;
    const int m0 = blockIdx.x * MT;
    const int n0 = blockIdx.y * NT;
    const int j0 = n0 >> 2;
    const int inPar = t & 1, outPar = inPar ^ 1;

    const __half* Ah = g_hs[inPar][0];
    const __half* Al = g_hs[inPar][1];
    const __half* Bh = g_Ws[mode][0];
    const __half* Bl = g_Ws[mode][1];

    float acc[4][4][4];
#pragma unroll
    for (int i = 0; i < 4; i++)
#pragma unroll
        for (int j = 0; j < 4; j++)
#pragma unroll
            for (int q = 0; q < 4; q++) acc[i][j][q] = 0.f;

    const int aRow = wm * 64 + (lane & 15);
    const int aCol = (lane >> 4) * 8;
    const int bRow = wn * 32 + ((lane & 16) >> 1) + (lane & 7);
    const int bCol = ((lane >> 3) & 1) * 8;

    load_stage(sb, 0, 0, Ah, Al, Bh, Bl, m0, n0, tid);
    cpa_commit();

    for (int kb = 0; kb < 4; kb++) {
        const int buf = kb & 1;
        if (kb < 3) {
            load_stage(sb, buf ^ 1, kb + 1, Ah, Al, Bh, Bl, m0, n0, tid);
            cpa_commit();
            cpa_wait<1>();
        } else {
            cpa_wait<0>();
        }
        __syncthreads();

        const uint32_t bAh = sb + buf * BUF_B;
        const uint32_t bAl = bAh + TILE_B;
        const uint32_t bBh = bAh + 2 * TILE_B;
        const uint32_t bBl = bAh + 3 * TILE_B;
#pragma unroll
        for (int k16 = 0; k16 < 4; k16++) {
            const uint32_t aOff = (uint32_t)(k16 * 16 + aCol) * 2;
            const uint32_t bOff = (uint32_t)(k16 * 16 + bCol) * 2;
            uint32_t ah[4][4], al[4][4], bh[2][4], bl[2][4];
#pragma unroll
            for (int mt = 0; mt < 4; mt++) {
                ldsm4(ah[mt], bAh + (uint32_t)(aRow + mt * 16) * TROW_B + aOff);
                ldsm4(al[mt], bAl + (uint32_t)(aRow + mt * 16) * TROW_B + aOff);
            }
#pragma unroll
            for (int bg = 0; bg < 2; bg++) {
                ldsm4(bh[bg], bBh + (uint32_t)(bRow + bg * 16) * TROW_B + bOff);
                ldsm4(bl[bg], bBl + (uint32_t)(bRow + bg * 16) * TROW_B + bOff);
            }
            // pass 1: Ah*Bh (16 independent MMAs)
#pragma unroll
            for (int mt = 0; mt < 4; mt++)
#pragma unroll
                for (int nt = 0; nt < 4; nt++) {
                    const int g = nt >> 1, s = (nt & 1) * 2;
                    mma16816(acc[mt][nt], ah[mt], bh[g][s], bh[g][s + 1]);
                }
            // pass 2: Ah*Bl
#pragma unroll
            for (int mt = 0; mt < 4; mt++)
#pragma unroll
                for (int nt = 0; nt < 4; nt++) {
                    const int g = nt >> 1, s = (nt & 1) * 2;
                    mma16816(acc[mt][nt], ah[mt], bl[g][s], bl[g][s + 1]);
                }
            // pass 3: Al*Bh
#pragma unroll
            for (int mt = 0; mt < 4; mt++)
#pragma unroll
                for (int nt = 0; nt < 4; nt++) {
                    const int g = nt >> 1, s = (nt & 1) * 2;
                    mma16816(acc[mt][nt], al[mt], bh[g][s], bh[g][s + 1]);
                }
        }
        __syncthreads();
    }

    // ---- stage accumulators to smem C (gate-interleaved columns) ----
#pragma unroll
    for (int mt = 0; mt < 4; mt++) {
#pragma unroll
        for (int nt = 0; nt < 4; nt++) {
            int r0 = wm * 64 + mt * 16 + (lane >> 2);
            int c0 = wn * 32 + nt * 8 + (lane & 3) * 2;
            *(float2*)&Cst[r0 * C_STRIDE + c0]       = make_float2(acc[mt][nt][0], acc[mt][nt][1]);
            *(float2*)&Cst[(r0 + 8) * C_STRIDE + c0] = make_float2(acc[mt][nt][2], acc[mt][nt][3]);
        }
    }
    __syncthreads();

    // ---- pointwise LSTM epilogue (fast exp-based activations) ----
    const float* projT = g_projP[mode];
#pragma unroll
    for (int i = 0; i < 16; i++) {
        int f = tid + i * 256;
        int lm = f >> 5, jl = f & 31;
        int m = m0 + lm;
        int tok = mode ? g_tok[m] : phon[m * TPH + t];
        float4 gv4 = *(const float4*)&Cst[lm * C_STRIDE + jl * 4];
        float4 pv  = *(const float4*)&projT[(size_t)tok * GDIM + (n0 + jl * 4)];
        float xi = gv4.x + pv.x;
        float xf = gv4.y + pv.y;
        float xg = gv4.z + pv.z;
        float xo = gv4.w + pv.w;
        float iv = fast_sigmoid(xi);
        float fv = fast_sigmoid(xf);
        float gg = fast_tanh(xg);
        float ov = fast_sigmoid(xo);
        size_t idx = (size_t)m * HDIM + j0 + jl;
        float cn = fv * g_c[idx] + iv * gg;
        g_c[idx] = cn;
        float hv = ov * fast_tanh(cn);
        __half hi = __float2half_rn(hv);
        __half lo = __float2half_rn(hv - __half2float(hi));
        g_hs[outPar][0][idx] = hi;
        g_hs[outPar][1][idx] = lo;
        if (mode) {
            g_hf[idx] = hv;
        } else if (t == lens[m] - 1) {
            g_eL[0][idx] = hi; g_eL[1][idx] = lo;
        }
    }
}

// ---------------- decoder fc + argmax: 16 rows/block (128 blocks) -----------
__global__ void __launch_bounds__(256)
dec_fc_kernel(const float* __restrict__ fcW,
              const float* __restrict__ fcb,
              float* __restrict__ out,
              int t)
{
    const float* h = g_hf;

    __shared__ float As[16][20];
    __shared__ float Bs[16][264];

    const int tid = threadIdx.x;
    const int tv = tid & 31;
    const int tm = tid >> 5;
    const int m0 = blockIdx.x * 16;

    float acc[2][8];
#pragma unroll
    for (int i = 0; i < 2; i++)
#pragma unroll
        for (int j = 0; j < 8; j++) acc[i][j] = 0.f;

    for (int k0 = 0; k0 < HDIM; k0 += 16) {
        if (tid < 64) {
            int r = tid >> 2, kq = tid & 3;
            float4 v = *(const float4*)(h + (size_t)(m0 + r) * HDIM + k0 + kq * 4);
            As[kq * 4 + 0][r] = v.x; As[kq * 4 + 1][r] = v.y;
            As[kq * 4 + 2][r] = v.z; As[kq * 4 + 3][r] = v.w;
        }
#pragma unroll
        for (int i = 0; i < 4; i++) {
            int f = tid + i * 256;
            int row = f >> 2, kq = f & 3;
            float4 v = *(const float4*)(fcW + (size_t)row * HDIM + k0 + kq * 4);
            Bs[kq * 4 + 0][row] = v.x; Bs[kq * 4 + 1][row] = v.y;
            Bs[kq * 4 + 2][row] = v.z; Bs[kq * 4 + 3][row] = v.w;
        }
        __syncthreads();
#pragma unroll
        for (int kk = 0; kk < 16; kk++) {
            float2 a  = *(const float2*)&As[kk][tm * 2];
            float4 b0 = *(const float4*)&Bs[kk][tv * 8];
            float4 b1 = *(const float4*)&Bs[kk][tv * 8 + 4];
            float bv[8] = {b0.x, b0.y, b0.z, b0.w, b1.x, b1.y, b1.z, b1.w};
#pragma unroll
            for (int vi = 0; vi < 8; vi++) {
                acc[0][vi] += a.x * bv[vi];
                acc[1][vi] += a.y * bv[vi];
            }
        }
        __syncthreads();
    }

    float bias[8];
#pragma unroll
    for (int vi = 0; vi < 8; vi++) bias[vi] = fcb[tv * 8 + vi];

#pragma unroll
    for (int mi = 0; mi < 2; mi++) {
        const int m = m0 + tm * 2 + mi;
        float s[8];
#pragma unroll
        for (int vi = 0; vi < 8; vi++) s[vi] = acc[mi][vi] + bias[vi];

        float* orow = out + (size_t)m * (TPH * VOC) + (size_t)t * VOC + tv * 8;
        *(float4*)(orow)     = make_float4(s[0], s[1], s[2], s[3]);
        *(float4*)(orow + 4) = make_float4(s[4], s[5], s[6], s[7]);

        float bv = s[0];
        int   bi = tv * 8;
#pragma unroll
        for (int vi = 1; vi < 8; vi++)
            if (s[vi] > bv) { bv = s[vi]; bi = tv * 8 + vi; }
#pragma unroll
        for (int off = 16; off > 0; off >>= 1) {
            float ov = __shfl_xor_sync(0xffffffffu, bv, off);
            int   oi = __shfl_xor_sync(0xffffffffu, bi, off);
            if (ov > bv || (ov == bv && oi < bi)) { bv = ov; bi = oi; }
        }
        if (tv == 0) g_tok[m] = bi;
    }
}

// ---------------- launch ----------------
extern "C" void kernel_launch(void* const* d_in, const int* in_sizes, int n_in,
                              void* d_out, int out_size)
{
    const int*   phon   = (const int*)  d_in[0];
    const int*   plen   = (const int*)  d_in[1];
    const float* emb    = (const float*)d_in[2];
    const float* encWih = (const float*)d_in[3];
    const float* encWhh = (const float*)d_in[4];
    const float* encBih = (const float*)d_in[5];
    const float* encBhh = (const float*)d_in[6];
    const float* decWih = (const float*)d_in[7];
    const float* decWhh = (const float*)d_in[8];
    const float* decBih = (const float*)d_in[9];
    const float* decBhh = (const float*)d_in[10];
    const float* fcW    = (const float*)d_in[11];
    const float* fcb    = (const float*)d_in[12];
    const int*   sos    = (const int*)  d_in[13];
    float* out = (float*)d_out;

    cudaFuncSetAttribute(lstm_step_mma,
                         cudaFuncAttributeMaxDynamicSharedMemorySize, SM_TOTAL);

    // launch #1..#3: prep (merged so lstm_step_mma lands in the ncu window)
    split_w_kernel<<<(2 * GDIM * HDIM + 255) / 256, 256>>>(encWhh, decWhh);
    dim3 pgrid(VOC, 4, 2);
    proj_kernel<<<pgrid, 256>>>(emb, encWih, encBih, encBhh, decWih, decBih, decBhh);
    init_kernel<<<(BT * HDIM + 255) / 256, 256>>>();

    dim3 grid(GRID_M, GRID_N);
    for (int t = 0; t < TPH; t++)
        lstm_step_mma<<<grid, 256, SM_TOTAL>>>(phon, plen, 0, t);

    dec_init_kernel<<<(BT * HDIM + 255) / 256, 256>>>(sos);

    for (int t = 0; t < TPH; t++) {
        lstm_step_mma<<<grid, 256, SM_TOTAL>>>(phon, plen, 1, t);
        dec_fc_kernel<<<BT / 16, 256>>>(fcW, fcb, out, t);
    }
}

// round 8
// speedup vs baseline: 1.1316x; 1.1316x over previous
#include <cuda_runtime.h>
#include <cuda_fp16.h>
#include <math.h>
#include <stdint.h>

#define BT   2048
#define TPH  32
#define EDIM 128
#define HDIM 256
#define GDIM 1024
#define VOC  256

// CTA tile: 128 M x 64 n' (16 units); grid 16 x 16 = 256 CTAs (2/SM)
#define MT 128
#define NTP 64
#define GRID_M (BT / MT)      // 16
#define GRID_N (GDIM / NTP)   // 16

// stage: k=32 halfs, padded row 40 halfs (80B)
#define AROW_B   80
#define A_TILE_B (128 * AROW_B)              // 10240
#define B_TILE_B (64 * AROW_B)               // 5120
#define STAGE_B  (2 * A_TILE_B + 2 * B_TILE_B) // 30720
#define NSTAGE   3
#define SM_TOTAL (NSTAGE * STAGE_B)          // 92160

// epilogue staging (reuses tile smem after mainloop)
#define ST_C   0        // float, stride 17
#define ST_HI  8704     // half, stride 18
#define ST_LO  13312
#define ST_HF  17920    // float, stride 17

// ---------------- device scratch ----------------
__device__ float   g_projP[2][VOC * GDIM];   // permuted proj tables (enc/dec)
__device__ __half  g_Ws[2][2][GDIM * HDIM];  // Whh fp16 splits (hi,lo), gate-interleaved rows
__device__ __half  g_hs[2][2][BT * HDIM];    // h fp16 splits, double buffered by parity
__device__ __half  g_eL[2][BT * HDIM];       // encoder-last h splits
__device__ float   g_c[BT * HDIM];
__device__ float   g_hf[BT * HDIM];          // fp32 h (decoder, for fc)
__device__ int     g_tok[BT];

// ---------------- fast pointwise (exp-based, ~1e-6 rel err) ----------------
__device__ __forceinline__ float fast_sigmoid(float x) {
    return __fdividef(1.f, 1.f + __expf(-x));
}
__device__ __forceinline__ float fast_tanh(float x) {
    return 1.f - __fdividef(2.f, __expf(2.f * x) + 1.f);
}

// ---------------- PTX helpers (portable: sm_80+) ----------------
__device__ __forceinline__ uint32_t smem_u32(const void* p) {
    uint32_t a;
    asm("{ .reg .u64 t; cvta.to.shared.u64 t, %1; cvt.u32.u64 %0, t; }" : "=r"(a) : "l"(p));
    return a;
}
__device__ __forceinline__ void cpa16(uint32_t saddr, const void* g) {
    asm volatile("cp.async.cg.shared.global [%0], [%1], 16;" :: "r"(saddr), "l"(g));
}
__device__ __forceinline__ void cpa_commit() {
    asm volatile("cp.async.commit_group;" ::: "memory");
}
template <int N>
__device__ __forceinline__ void cpa_wait() {
    asm volatile("cp.async.wait_group %0;" :: "n"(N) : "memory");
}
__device__ __forceinline__ void ldsm4(uint32_t* r, uint32_t addr) {
    asm volatile("ldmatrix.sync.aligned.m8n8.x4.shared.b16 {%0,%1,%2,%3}, [%4];"
        : "=r"(r[0]), "=r"(r[1]), "=r"(r[2]), "=r"(r[3]) : "r"(addr));
}
__device__ __forceinline__ void mma16816(float* c, const uint32_t* a,
                                         uint32_t b0, uint32_t b1) {
    asm volatile("mma.sync.aligned.m16n8k16.row.col.f32.f16.f16.f32 "
        "{%0,%1,%2,%3}, {%4,%5,%6,%7}, {%8,%9}, {%0,%1,%2,%3};"
        : "+f"(c[0]), "+f"(c[1]), "+f"(c[2]), "+f"(c[3])
        : "r"(a[0]), "r"(a[1]), "r"(a[2]), "r"(a[3]), "r"(b0), "r"(b1));
}

// ---------------- prep #1: split BOTH Whh into 2 fp16 planes, gate-interleaved
__global__ void split_w_kernel(const float* __restrict__ Wenc,
                               const float* __restrict__ Wdec)
{
    int gidx = blockIdx.x * blockDim.x + threadIdx.x;   // over 2*GDIM*HDIM
    if (gidx >= 2 * GDIM * HDIM) return;
    int which = gidx >= GDIM * HDIM;
    int idx = gidx - which * (GDIM * HDIM);
    const float* W = which ? Wdec : Wenc;
    int np = idx >> 8, k = idx & 255;
    int j = np >> 2, g = np & 3;                        // n' = j*4 + g
    float w = W[(size_t)(g * HDIM + j) * HDIM + k];
    __half hi = __float2half_rn(w);
    __half lo = __float2half_rn(w - __half2float(hi));
    g_Ws[which][0][idx] = hi;
    g_Ws[which][1][idx] = lo;
}

// ---------------- prep #2: permuted proj tables (both enc & dec) ------------
__global__ void proj_kernel(const float* __restrict__ emb,
                            const float* __restrict__ Wenc,
                            const float* __restrict__ b1e,
                            const float* __restrict__ b2e,
                            const float* __restrict__ Wdec,
                            const float* __restrict__ b1d,
                            const float* __restrict__ b2d)
{
    int which = blockIdx.z;
    const float* W  = which ? Wdec : Wenc;
    const float* b1 = which ? b1d : b1e;
    const float* b2 = which ? b2d : b2e;
    int v = blockIdx.x;
    __shared__ float es[EDIM];
    int tid = threadIdx.x;
    if (tid < EDIM) es[tid] = emb[v * EDIM + tid];
    __syncthreads();
    int n = blockIdx.y * 256 + tid;
    const float4* wr = (const float4*)(W + (size_t)n * EDIM);
    float a0 = 0.f, a1 = 0.f, a2 = 0.f, a3 = 0.f;   // 4 chains break FFMA latency
#pragma unroll
    for (int k4 = 0; k4 < EDIM / 16; k4++) {
        float4 w0 = wr[k4 * 4 + 0];
        float4 w1 = wr[k4 * 4 + 1];
        float4 w2 = wr[k4 * 4 + 2];
        float4 w3 = wr[k4 * 4 + 3];
        const float* e = es + k4 * 16;
        a0 += e[0] * w0.x + e[1] * w0.y + e[2] * w0.z + e[3] * w0.w;
        a1 += e[4] * w1.x + e[5] * w1.y + e[6] * w1.z + e[7] * w1.w;
        a2 += e[8] * w2.x + e[9] * w2.y + e[10] * w2.z + e[11] * w2.w;
        a3 += e[12] * w3.x + e[13] * w3.y + e[14] * w3.z + e[15] * w3.w;
    }
    int np = (n & 255) * 4 + (n >> 8);
    g_projP[which][(size_t)v * GDIM + np] = (a0 + a1) + (a2 + a3) + b1[n] + b2[n];
}

// ---------------- init / dec-init ----------------
__global__ void init_kernel()
{
    int i = blockIdx.x * blockDim.x + threadIdx.x;
    if (i < BT * HDIM) {
        __half z = __float2half_rn(0.f);
        g_hs[0][0][i] = z; g_hs[0][1][i] = z;
        g_c[i] = 0.f;
    }
}
__global__ void dec_init_kernel(const int* __restrict__ sos)
{
    int i = blockIdx.x * blockDim.x + threadIdx.x;
    if (i < BT * HDIM) {
        g_hs[0][0][i] = g_eL[0][i];
        g_hs[0][1][i] = g_eL[1][i];
        g_c[i] = 0.f;
    }
    if (i < BT) g_tok[i] = sos[0];
}

// ---------------- stage loader: Ah, Al (128x32) + Bh, Bl (64x32), k-block kb -
__device__ __forceinline__ void load_stage(
    uint32_t base, int kb,
    const __half* __restrict__ Ah, const __half* __restrict__ Al,
    const __half* __restrict__ Bh, const __half* __restrict__ Bl,
    int m0, int n0, int tid)
{
    // A tiles: row = tid>>1, two cpa16 at (tid&1)*32B
    {
        const int row = tid >> 1;
        const int h0 = (tid & 1) * 16;                       // halfs
        const size_t gsrc = (size_t)(m0 + row) * HDIM + kb * 32 + h0;
        const uint32_t sdst = base + (uint32_t)(row * AROW_B + h0 * 2);
        cpa16(sdst,                 Ah + gsrc);
        cpa16(sdst + 16,            Ah + gsrc + 8);
        cpa16(sdst + A_TILE_B,      Al + gsrc);
        cpa16(sdst + A_TILE_B + 16, Al + gsrc + 8);
    }
    // B tiles: row = tid>>2, one cpa16 at (tid&3)*16B
    {
        const int row = tid >> 2;
        const int q = tid & 3;
        const size_t gsrc = (size_t)(n0 + row) * HDIM + kb * 32 + q * 8;
        const uint32_t sdst = base + 2 * A_TILE_B + (uint32_t)(row * AROW_B + q * 16);
        cpa16(sdst,            Bh + gsrc);
        cpa16(sdst + B_TILE_B, Bl + gsrc);
    }
}

// ---------------- fused LSTM step -------------------------------------------
// C = Ah.Bh + Ah.Bl + Al.Bh ; CTA 128x64, 8 warps (2M x 4N), warp 64x16.
// 3-stage cp.async pipeline (k=32), shuffle epilogue, coalesced writeout.
__global__ void __launch_bounds__(256, 2)
lstm_step_mma(const int* __restrict__ phon, const int* __restrict__ lens,
              int mode, int t)
{
    extern __shared__ char smem[];
    const uint32_t sb = smem_u32(smem);

    const int tid  = threadIdx.x;
    const int lane = tid & 31;
    const int wid  = tid >> 5;
    const int wm = wid & 1, wn = wid >> 1;
    const int m0 = blockIdx.x * MT;
    const int n0 = blockIdx.y * NTP;
    const int j0g = blockIdx.y * 16;
    const int inPar = t & 1, outPar = inPar ^ 1;

    const __half* Ah = g_hs[inPar][0];
    const __half* Al = g_hs[inPar][1];
    const __half* Bh = g_Ws[mode][0];
    const __half* Bl = g_Ws[mode][1];

    // ---- preload c + tokens into registers (latency hidden by whole GEMM) --
    const int myRow = wm * 64 + (lane >> 2) + (lane & 1) * 8;   // + mt*16
    const int myUl  = wn * 4 + ((lane & 2) >> 1);               // + nt*2
    float cpre[4][2];
    int   tokr[4];
#pragma unroll
    for (int mt = 0; mt < 4; mt++) {
        const int m = m0 + myRow + mt * 16;
        tokr[mt] = mode ? g_tok[m] : phon[m * TPH + t];
#pragma unroll
        for (int nt = 0; nt < 2; nt++)
            cpre[mt][nt] = g_c[(size_t)m * HDIM + j0g + myUl + nt * 2];
    }

    float acc[4][2][4];
#pragma unroll
    for (int i = 0; i < 4; i++)
#pragma unroll
        for (int j = 0; j < 2; j++)
#pragma unroll
            for (int q = 0; q < 4; q++) acc[i][j][q] = 0.f;

    const int aRow = wm * 64 + (lane & 15);
    const int aCol = (lane >> 4) * 8;
    const int bRow = wn * 16 + ((lane & 16) >> 1) + (lane & 7);
    const int bColH = ((lane >> 3) & 1) * 8;

    // ---- prologue: stages 0 and 1 ----
    load_stage(sb, 0, Ah, Al, Bh, Bl, m0, n0, tid);
    cpa_commit();
    load_stage(sb + STAGE_B, 1, Ah, Al, Bh, Bl, m0, n0, tid);
    cpa_commit();

    int bufOff[3] = {0, STAGE_B, 2 * STAGE_B};
    for (int kb = 0; kb < 8; kb++) {
        if (kb < 6) {
            load_stage(sb + bufOff[(kb + 2) % 3], kb + 2, Ah, Al, Bh, Bl, m0, n0, tid);
            cpa_commit();
            cpa_wait<2>();
        } else if (kb == 6) {
            cpa_wait<1>();
        } else {
            cpa_wait<0>();
        }
        __syncthreads();

        const uint32_t bAh = sb + bufOff[kb % 3];
        const uint32_t bAl = bAh + A_TILE_B;
        const uint32_t bBh = bAh + 2 * A_TILE_B;
        const uint32_t bBl = bBh + B_TILE_B;
#pragma unroll
        for (int k16 = 0; k16 < 2; k16++) {
            const uint32_t aOff = (uint32_t)(k16 * 16 + aCol) * 2;
            const uint32_t bOff = (uint32_t)(k16 * 16 + bColH) * 2;
            uint32_t ah[4][4], al[4][4], bh[4], bl[4];
#pragma unroll
            for (int mt = 0; mt < 4; mt++) {
                ldsm4(ah[mt], bAh + (uint32_t)(aRow + mt * 16) * AROW_B + aOff);
                ldsm4(al[mt], bAl + (uint32_t)(aRow + mt * 16) * AROW_B + aOff);
            }
            ldsm4(bh, bBh + (uint32_t)bRow * AROW_B + bOff);
            ldsm4(bl, bBl + (uint32_t)bRow * AROW_B + bOff);
            // pass 1: Ah*Bh (8 independent)
#pragma unroll
            for (int mt = 0; mt < 4; mt++)
#pragma unroll
                for (int nt = 0; nt < 2; nt++)
                    mma16816(acc[mt][nt], ah[mt], bh[nt * 2], bh[nt * 2 + 1]);
            // pass 2: Ah*Bl
#pragma unroll
            for (int mt = 0; mt < 4; mt++)
#pragma unroll
                for (int nt = 0; nt < 2; nt++)
                    mma16816(acc[mt][nt], ah[mt], bl[nt * 2], bl[nt * 2 + 1]);
            // pass 3: Al*Bh
#pragma unroll
            for (int mt = 0; mt < 4; mt++)
#pragma unroll
                for (int nt = 0; nt < 2; nt++)
                    mma16816(acc[mt][nt], al[mt], bh[nt * 2], bh[nt * 2 + 1]);
        }
        __syncthreads();
    }

    // ---- shuffle epilogue: gather 4 gates/unit into one thread -------------
    // fragment (mt,nt): c0,c1 = (row r, n' q*2, q*2+1); c2,c3 = (r+8, same).
    // even lane(q even) -> row r; odd -> row r+8; pair exchange via shfl_xor(1).
    float* SC  = (float*)(smem + ST_C);
    __half* SHI = (__half*)(smem + ST_HI);
    __half* SLO = (__half*)(smem + ST_LO);
    float* SHF = (float*)(smem + ST_HF);
    const float* projT = g_projP[mode];
    const bool odd = (lane & 1);

#pragma unroll
    for (int mt = 0; mt < 4; mt++) {
        const float4 pv = *(const float4*)&projT[(size_t)tokr[mt] * GDIM
                                                 + (n0 + (myUl + 0) * 4)];
        const float4 pv2 = *(const float4*)&projT[(size_t)tokr[mt] * GDIM
                                                  + (n0 + (myUl + 2) * 4)];
#pragma unroll
        for (int nt = 0; nt < 2; nt++) {
            float c0 = acc[mt][nt][0], c1 = acc[mt][nt][1];
            float c2 = acc[mt][nt][2], c3 = acc[mt][nt][3];
            float sA = odd ? c0 : c2;
            float sB = odd ? c1 : c3;
            float rA = __shfl_xor_sync(0xffffffffu, sA, 1);
            float rB = __shfl_xor_sync(0xffffffffu, sB, 1);
            float gi = odd ? rA : c0;
            float gf = odd ? rB : c1;
            float gg = odd ? c2 : rA;
            float go = odd ? c3 : rB;
            const float4 p = nt ? pv2 : pv;
            float xi = gi + p.x;
            float xf = gf + p.y;
            float xg = gg + p.z;
            float xo = go + p.w;
            float iv = fast_sigmoid(xi);
            float fv = fast_sigmoid(xf);
            float gv = fast_tanh(xg);
            float ov = fast_sigmoid(xo);
            float cn = fv * cpre[mt][nt] + iv * gv;
            float hv = ov * fast_tanh(cn);
            const int lr = myRow + mt * 16;
            const int ul = myUl + nt * 2;
            SC[lr * 17 + ul] = cn;
            __half hi = __float2half_rn(hv);
            __half lo = __float2half_rn(hv - __half2float(hi));
            SHI[lr * 18 + ul] = hi;
            SLO[lr * 18 + ul] = lo;
            SHF[lr * 17 + ul] = hv;
        }
    }
    __syncthreads();

    // ---- coalesced writeout ----
    __half* outHi = g_hs[outPar][0];
    __half* outLo = g_hs[outPar][1];
#pragma unroll
    for (int i = 0; i < 8; i++) {
        int f = tid + i * 256;
        int lm = f >> 4, jl = f & 15;
        size_t gidx = (size_t)(m0 + lm) * HDIM + j0g + jl;
        g_c[gidx] = SC[lm * 17 + jl];
        __half hi = SHI[lm * 18 + jl];
        __half lo = SLO[lm * 18 + jl];
        outHi[gidx] = hi;
        outLo[gidx] = lo;
        if (mode) {
            g_hf[gidx] = SHF[lm * 17 + jl];
        } else if (t == lens[m0 + lm] - 1) {
            g_eL[0][gidx] = hi;
            g_eL[1][gidx] = lo;
        }
    }
}

// ---------------- decoder fc + argmax: 16 rows/block (128 blocks) -----------
__global__ void __launch_bounds__(256)
dec_fc_kernel(const float* __restrict__ fcW,
              const float* __restrict__ fcb,
              float* __restrict__ out,
              int t)
{
    const float* h = g_hf;

    __shared__ float As[16][20];
    __shared__ float Bs[16][264];

    const int tid = threadIdx.x;
    const int tv = tid & 31;
    const int tm = tid >> 5;
    const int m0 = blockIdx.x * 16;

    float acc[2][8];
#pragma unroll
    for (int i = 0; i < 2; i++)
#pragma unroll
        for (int j = 0; j < 8; j++) acc[i][j] = 0.f;

    for (int k0 = 0; k0 < HDIM; k0 += 16) {
        if (tid < 64) {
            int r = tid >> 2, kq = tid & 3;
            float4 v = *(const float4*)(h + (size_t)(m0 + r) * HDIM + k0 + kq * 4);
            As[kq * 4 + 0][r] = v.x; As[kq * 4 + 1][r] = v.y;
            As[kq * 4 + 2][r] = v.z; As[kq * 4 + 3][r] = v.w;
        }
#pragma unroll
        for (int i = 0; i < 4; i++) {
            int f = tid + i * 256;
            int row = f >> 2, kq = f & 3;
            float4 v = *(const float4*)(fcW + (size_t)row * HDIM + k0 + kq * 4);
            Bs[kq * 4 + 0][row] = v.x; Bs[kq * 4 + 1][row] = v.y;
            Bs[kq * 4 + 2][row] = v.z; Bs[kq * 4 + 3][row] = v.w;
        }
        __syncthreads();
#pragma unroll
        for (int kk = 0; kk < 16; kk++) {
            float2 a  = *(const float2*)&As[kk][tm * 2];
            float4 b0 = *(const float4*)&Bs[kk][tv * 8];
            float4 b1 = *(const float4*)&Bs[kk][tv * 8 + 4];
            float bv[8] = {b0.x, b0.y, b0.z, b0.w, b1.x, b1.y, b1.z, b1.w};
#pragma unroll
            for (int vi = 0; vi < 8; vi++) {
                acc[0][vi] += a.x * bv[vi];
                acc[1][vi] += a.y * bv[vi];
            }
        }
        __syncthreads();
    }

    float bias[8];
#pragma unroll
    for (int vi = 0; vi < 8; vi++) bias[vi] = fcb[tv * 8 + vi];

#pragma unroll
    for (int mi = 0; mi < 2; mi++) {
        const int m = m0 + tm * 2 + mi;
        float s[8];
#pragma unroll
        for (int vi = 0; vi < 8; vi++) s[vi] = acc[mi][vi] + bias[vi];

        float* orow = out + (size_t)m * (TPH * VOC) + (size_t)t * VOC + tv * 8;
        *(float4*)(orow)     = make_float4(s[0], s[1], s[2], s[3]);
        *(float4*)(orow + 4) = make_float4(s[4], s[5], s[6], s[7]);

        float bv = s[0];
        int   bi = tv * 8;
#pragma unroll
        for (int vi = 1; vi < 8; vi++)
            if (s[vi] > bv) { bv = s[vi]; bi = tv * 8 + vi; }
#pragma unroll
        for (int off = 16; off > 0; off >>= 1) {
            float ov = __shfl_xor_sync(0xffffffffu, bv, off);
            int   oi = __shfl_xor_sync(0xffffffffu, bi, off);
            if (ov > bv || (ov == bv && oi < bi)) { bv = ov; bi = oi; }
        }
        if (tv == 0) g_tok[m] = bi;
    }
}

// ---------------- launch ----------------
extern "C" void kernel_launch(void* const* d_in, const int* in_sizes, int n_in,
                              void* d_out, int out_size)
{
    const int*   phon   = (const int*)  d_in[0];
    const int*   plen   = (const int*)  d_in[1];
    const float* emb    = (const float*)d_in[2];
    const float* encWih = (const float*)d_in[3];
    const float* encWhh = (const float*)d_in[4];
    const float* encBih = (const float*)d_in[5];
    const float* encBhh = (const float*)d_in[6];
    const float* decWih = (const float*)d_in[7];
    const float* decWhh = (const float*)d_in[8];
    const float* decBih = (const float*)d_in[9];
    const float* decBhh = (const float*)d_in[10];
    const float* fcW    = (const float*)d_in[11];
    const float* fcb    = (const float*)d_in[12];
    const int*   sos    = (const int*)  d_in[13];
    float* out = (float*)d_out;

    cudaFuncSetAttribute(lstm_step_mma,
                         cudaFuncAttributeMaxDynamicSharedMemorySize, SM_TOTAL);

    split_w_kernel<<<(2 * GDIM * HDIM + 255) / 256, 256>>>(encWhh, decWhh);
    dim3 pgrid(VOC, 4, 2);
    proj_kernel<<<pgrid, 256>>>(emb, encWih, encBih, encBhh, decWih, decBih, decBhh);
    init_kernel<<<(BT * HDIM + 255) / 256, 256>>>();

    dim3 grid(GRID_M, GRID_N);
    for (int t = 0; t < TPH; t++)
        lstm_step_mma<<<grid, 256, SM_TOTAL>>>(phon, plen, 0, t);

    dec_init_kernel<<<(BT * HDIM + 255) / 256, 256>>>(sos);

    for (int t = 0; t < TPH; t++) {
        lstm_step_mma<<<grid, 256, SM_TOTAL>>>(phon, plen, 1, t);
        dec_fc_kernel<<<BT / 16, 256>>>(fcW, fcb, out, t);
    }
}

// round 9
// speedup vs baseline: 1.5421x; 1.3627x over previous
#include <cuda_runtime.h>
#include <cuda_fp16.h>
#include <stdint.h>

#define BT   2048
#define TPH  32
#define EDIM 128
#define HDIM 256
#define GDIM 1024
#define VOC  256

#define NCTA 128          // 16 m-blocks x 8 n-blocks, 1 CTA/SM (co-resident)
#define MT   128
#define NTP  128          // n' (gate-interleaved) per CTA

// ---------------- smem map (bytes) ----------------
#define W_ROW_B   528                    // 256 halfs + 8 pad
#define W_PLANE_B (128 * W_ROW_B)        // 67584
#define SM_W      0
#define SM_STG    (2 * W_PLANE_B)        // 135168
#define SM_STG_B  66560
// LSTM A stages: 3 x 20480 (chunk = 2 planes x 128 rows x 80B)
#define A_PL_B    10240
#define A_CH_B    20480
// fc: fcA 2x8448 @SM_STG ; fcB 2 bufs x 24576 after
#define FCA_PL_B  8448
#define FCB_OFF   (SM_STG + 16896)
#define FCB_BUF_B 24576
#define FCB_PL_B  12288
#define SSC_OFF   (SM_STG + 16896)       // scores 16x264 f32 (after fc GEMM)
// epilogue h staging (overlays stage region)
#define SHI_OFF   SM_STG
#define SLO_OFF   (SM_STG + 8704)        // 128*68
#define SM_FCBIA  (SM_STG + SM_STG_B)    // 256 f32 bias
#define SM_TOTAL  (SM_FCBIA + 1024)      // 202752

// ---------------- device scratch ----------------
__device__ float   g_projP[2][VOC * GDIM];
__device__ __half  g_Ws[2][2][GDIM * HDIM];    // Whh splits, gate-interleaved
__device__ __half  g_fcWs[2][VOC * HDIM];      // fcW splits, v-major
__device__ __half  g_hs[2][2][BT * HDIM];      // h splits by parity
__device__ __half  g_eL[2][BT * HDIM];
__device__ int     g_tok[BT];
__device__ unsigned          g_bar_cnt = 0;
__device__ volatile unsigned g_bar_sense = 0;

// ---------------- fast pointwise ----------------
__device__ __forceinline__ float fast_sigmoid(float x) {
    return __fdividef(1.f, 1.f + __expf(-x));
}
__device__ __forceinline__ float fast_tanh(float x) {
    return 1.f - __fdividef(2.f, __expf(2.f * x) + 1.f);
}

// ---------------- PTX helpers ----------------
__device__ __forceinline__ uint32_t smem_u32(const void* p) {
    uint32_t a;
    asm("{ .reg .u64 t; cvta.to.shared.u64 t, %1; cvt.u32.u64 %0, t; }" : "=r"(a) : "l"(p));
    return a;
}
__device__ __forceinline__ void cpa16(uint32_t saddr, const void* g) {
    asm volatile("cp.async.cg.shared.global [%0], [%1], 16;" :: "r"(saddr), "l"(g));
}
__device__ __forceinline__ void cpa_commit() {
    asm volatile("cp.async.commit_group;" ::: "memory");
}
template <int N>
__device__ __forceinline__ void cpa_wait() {
    asm volatile("cp.async.wait_group %0;" :: "n"(N) : "memory");
}
__device__ __forceinline__ void ldsm4(uint32_t* r, uint32_t addr) {
    asm volatile("ldmatrix.sync.aligned.m8n8.x4.shared.b16 {%0,%1,%2,%3}, [%4];"
        : "=r"(r[0]), "=r"(r[1]), "=r"(r[2]), "=r"(r[3]) : "r"(addr));
}
__device__ __forceinline__ void mma16816(float* c, const uint32_t* a,
                                         uint32_t b0, uint32_t b1) {
    asm volatile("mma.sync.aligned.m16n8k16.row.col.f32.f16.f16.f32 "
        "{%0,%1,%2,%3}, {%4,%5,%6,%7}, {%8,%9}, {%0,%1,%2,%3};"
        : "+f"(c[0]), "+f"(c[1]), "+f"(c[2]), "+f"(c[3])
        : "r"(a[0]), "r"(a[1]), "r"(a[2]), "r"(a[3]), "r"(b0), "r"(b1));
}

// ---------------- grid barrier (sense-reversing; even flips per launch) -----
__device__ __forceinline__ void grid_sync(unsigned& sense) {
    sense ^= 1u;
    __syncthreads();
    if (threadIdx.x == 0) {
        __threadfence();
        if (atomicAdd(&g_bar_cnt, 1u) == NCTA - 1) {
            g_bar_cnt = 0;
            __threadfence();
            g_bar_sense = sense;
        } else {
            while (g_bar_sense != sense) __nanosleep(32);
        }
        __threadfence();
    }
    __syncthreads();
}

// ---------------- prep kernels ----------------
__global__ void split_w_kernel(const float* __restrict__ Wenc,
                               const float* __restrict__ Wdec)
{
    int gidx = blockIdx.x * blockDim.x + threadIdx.x;
    if (gidx >= 2 * GDIM * HDIM) return;
    int which = gidx >= GDIM * HDIM;
    int idx = gidx - which * (GDIM * HDIM);
    const float* W = which ? Wdec : Wenc;
    int np = idx >> 8, k = idx & 255;
    int j = np >> 2, g = np & 3;
    float w = W[(size_t)(g * HDIM + j) * HDIM + k];
    __half hi = __float2half_rn(w);
    __half lo = __float2half_rn(w - __half2float(hi));
    g_Ws[which][0][idx] = hi;
    g_Ws[which][1][idx] = lo;
}

__global__ void split_fc_kernel(const float* __restrict__ fcW)
{
    int idx = blockIdx.x * blockDim.x + threadIdx.x;
    if (idx >= VOC * HDIM) return;
    float w = fcW[idx];
    __half hi = __float2half_rn(w);
    __half lo = __float2half_rn(w - __half2float(hi));
    g_fcWs[0][idx] = hi;
    g_fcWs[1][idx] = lo;
}

__global__ void proj_kernel(const float* __restrict__ emb,
                            const float* __restrict__ Wenc,
                            const float* __restrict__ b1e,
                            const float* __restrict__ b2e,
                            const float* __restrict__ Wdec,
                            const float* __restrict__ b1d,
                            const float* __restrict__ b2d)
{
    int which = blockIdx.z;
    const float* W  = which ? Wdec : Wenc;
    const float* b1 = which ? b1d : b1e;
    const float* b2 = which ? b2d : b2e;
    int v = blockIdx.x;
    __shared__ float es[EDIM];
    int tid = threadIdx.x;
    if (tid < EDIM) es[tid] = emb[v * EDIM + tid];
    __syncthreads();
    int n = blockIdx.y * 256 + tid;
    const float4* wr = (const float4*)(W + (size_t)n * EDIM);
    float a0 = 0.f, a1 = 0.f, a2 = 0.f, a3 = 0.f;
#pragma unroll
    for (int k4 = 0; k4 < EDIM / 16; k4++) {
        float4 w0 = wr[k4 * 4 + 0];
        float4 w1 = wr[k4 * 4 + 1];
        float4 w2 = wr[k4 * 4 + 2];
        float4 w3 = wr[k4 * 4 + 3];
        const float* e = es + k4 * 16;
        a0 += e[0] * w0.x + e[1] * w0.y + e[2] * w0.z + e[3] * w0.w;
        a1 += e[4] * w1.x + e[5] * w1.y + e[6] * w1.z + e[7] * w1.w;
        a2 += e[8] * w2.x + e[9] * w2.y + e[10] * w2.z + e[11] * w2.w;
        a3 += e[12] * w3.x + e[13] * w3.y + e[14] * w3.z + e[15] * w3.w;
    }
    int np = (n & 255) * 4 + (n >> 8);
    g_projP[which][(size_t)v * GDIM + np] = (a0 + a1) + (a2 + a3) + b1[n] + b2[n];
}

__global__ void init_kernel()
{
    int i = blockIdx.x * blockDim.x + threadIdx.x;
    if (i < BT * HDIM) {
        __half z = __float2half_rn(0.f);
        g_hs[0][0][i] = z; g_hs[0][1][i] = z;
    }
}

// ---------------- persistent kernel ----------------
__global__ void __launch_bounds__(256, 1)
persist_kernel(const int* __restrict__ phon, const int* __restrict__ lens,
               const float* __restrict__ fcb, const int* __restrict__ sos,
               float* __restrict__ out)
{
    extern __shared__ char smem[];
    const uint32_t sb = smem_u32(smem);

    const int tid  = threadIdx.x;
    const int lane = tid & 31;
    const int wid  = tid >> 5;
    const int wm = wid & 1, wn = wid >> 1;
    const int bm = blockIdx.x >> 3, bn = blockIdx.x & 7;
    const int m0 = bm * MT;
    const int n0 = bn * NTP;
    const int j0g = bn * 32;
    const int r0fc = blockIdx.x * 16;

    unsigned sense = 0;
    const int sos0 = sos[0];

    // fc bias into smem
    ((float*)(smem + SM_FCBIA))[tid] = fcb[tid];

    // fragment / epilogue ownership
    const int aRow = wm * 64 + (lane & 15);
    const int aCol = (lane >> 4) * 8;
    const int bRow = wn * 32 + ((lane & 16) >> 1) + (lane & 7);
    const int bColH = ((lane >> 3) & 1) * 8;
    const int myRow = wm * 64 + (lane >> 2) + (lane & 1) * 8;
    const int myUlB = wn * 8 + ((lane & 2) >> 1);
    const bool odd = (lane & 1);

    // resident W loader (mode)
    auto load_W = [&](int mode) {
        for (int f = tid; f < 8192; f += 256) {
            int p = f >> 12, rem = f & 4095;
            int row = rem >> 5, seg = rem & 31;
            cpa16(sb + SM_W + p * W_PLANE_B + row * W_ROW_B + seg * 16,
                  g_Ws[mode][p] + (size_t)(n0 + row) * HDIM + seg * 8);
        }
        cpa_commit();
        cpa_wait<0>();
        __syncthreads();
    };
    load_W(0);

    // per-thread persistent c
    float cpre[4][4];
#pragma unroll
    for (int i = 0; i < 4; i++)
#pragma unroll
        for (int j = 0; j < 4; j++) cpre[i][j] = 0.f;

    // encoder lens preload (for eL condition in writeout we read global)
    for (int t = 0; t < 2 * TPH; t++) {
        const int mode = (t >= TPH);
        if (t == TPH) {
            load_W(1);
#pragma unroll
            for (int i = 0; i < 4; i++)
#pragma unroll
                for (int j = 0; j < 4; j++) cpre[i][j] = 0.f;
        }
        const int inPar = t & 1, outPar = inPar ^ 1;
        const __half* A0 = (t == TPH) ? g_eL[0] : g_hs[inPar][0];
        const __half* A1 = (t == TPH) ? g_eL[1] : g_hs[inPar][1];

        // prefetch tokens (available since last barrier)
        int tokr[4];
#pragma unroll
        for (int mt = 0; mt < 4; mt++) {
            const int m = m0 + myRow + mt * 16;
            tokr[mt] = mode ? ((t == TPH) ? sos0 : g_tok[m]) : phon[m * TPH + t];
        }

        float acc[4][4][4];
#pragma unroll
        for (int i = 0; i < 4; i++)
#pragma unroll
            for (int j = 0; j < 4; j++)
#pragma unroll
                for (int q = 0; q < 4; q++) acc[i][j][q] = 0.f;

        // A chunk loader
        auto load_a = [&](int stg, int kb) {
            const int row = tid >> 1;
            const int half = tid & 1;
            const uint32_t d0 = sb + SM_STG + stg * A_CH_B + row * 80 + half * 32;
            const size_t s0 = (size_t)(m0 + row) * HDIM + kb * 32 + half * 16;
            cpa16(d0,                    A0 + s0);
            cpa16(d0 + 16,               A0 + s0 + 8);
            cpa16(d0 + A_PL_B,           A1 + s0);
            cpa16(d0 + A_PL_B + 16,      A1 + s0 + 8);
        };

        load_a(0, 0); cpa_commit();
        load_a(1, 1); cpa_commit();

        for (int kb = 0; kb < 8; kb++) {
            if (kb < 6) {
                load_a((kb + 2) % 3, kb + 2);
                cpa_commit();
                cpa_wait<2>();
            } else if (kb == 6) {
                cpa_wait<1>();
            } else {
                cpa_wait<0>();
            }
            __syncthreads();

            const uint32_t bA = sb + SM_STG + (kb % 3) * A_CH_B;
#pragma unroll
            for (int k16 = 0; k16 < 2; k16++) {
                const uint32_t aOff = (uint32_t)(k16 * 16 + aCol) * 2;
                const uint32_t kW = (uint32_t)(kb * 32 + k16 * 16 + bColH) * 2;
                uint32_t ah[4][4], al[4][4], bh[2][4], bl[2][4];
#pragma unroll
                for (int mt = 0; mt < 4; mt++) {
                    ldsm4(ah[mt], bA + (uint32_t)(aRow + mt * 16) * 80 + aOff);
                    ldsm4(al[mt], bA + A_PL_B + (uint32_t)(aRow + mt * 16) * 80 + aOff);
                }
#pragma unroll
                for (int bg = 0; bg < 2; bg++) {
                    ldsm4(bh[bg], sb + SM_W + (uint32_t)(bRow + bg * 16) * W_ROW_B + kW);
                    ldsm4(bl[bg], sb + SM_W + W_PLANE_B
                                   + (uint32_t)(bRow + bg * 16) * W_ROW_B + kW);
                }
#pragma unroll
                for (int mt = 0; mt < 4; mt++)
#pragma unroll
                    for (int nt = 0; nt < 4; nt++) {
                        const int g = nt >> 1, s = (nt & 1) * 2;
                        mma16816(acc[mt][nt], ah[mt], bh[g][s], bh[g][s + 1]);
                    }
#pragma unroll
                for (int mt = 0; mt < 4; mt++)
#pragma unroll
                    for (int nt = 0; nt < 4; nt++) {
                        const int g = nt >> 1, s = (nt & 1) * 2;
                        mma16816(acc[mt][nt], ah[mt], bl[g][s], bl[g][s + 1]);
                    }
#pragma unroll
                for (int mt = 0; mt < 4; mt++)
#pragma unroll
                    for (int nt = 0; nt < 4; nt++) {
                        const int g = nt >> 1, s = (nt & 1) * 2;
                        mma16816(acc[mt][nt], al[mt], bh[g][s], bh[g][s + 1]);
                    }
            }
            __syncthreads();
        }

        // ---- epilogue: shuffle gates, activations, c in regs ----
        __half* SHI = (__half*)(smem + SHI_OFF);
        __half* SLO = (__half*)(smem + SLO_OFF);
        const float* projT = g_projP[mode];
#pragma unroll
        for (int mt = 0; mt < 4; mt++) {
#pragma unroll
            for (int nt = 0; nt < 4; nt++) {
                const int ul = myUlB + nt * 2;
                const float4 p = *(const float4*)&projT[(size_t)tokr[mt] * GDIM
                                                        + n0 + ul * 4];
                float c0 = acc[mt][nt][0], c1 = acc[mt][nt][1];
                float c2 = acc[mt][nt][2], c3 = acc[mt][nt][3];
                float sA = odd ? c0 : c2;
                float sB = odd ? c1 : c3;
                float rA = __shfl_xor_sync(0xffffffffu, sA, 1);
                float rB = __shfl_xor_sync(0xffffffffu, sB, 1);
                float gi = odd ? rA : c0;
                float gf = odd ? rB : c1;
                float gg = odd ? c2 : rA;
                float go = odd ? c3 : rB;
                float iv = fast_sigmoid(gi + p.x);
                float fv = fast_sigmoid(gf + p.y);
                float gv = fast_tanh(gg + p.z);
                float ov = fast_sigmoid(go + p.w);
                float cn = fv * cpre[mt][nt] + iv * gv;
                cpre[mt][nt] = cn;
                float hv = ov * fast_tanh(cn);
                __half hi = __float2half_rn(hv);
                __half lo = __float2half_rn(hv - __half2float(hi));
                const int lr = myRow + mt * 16;
                SHI[lr * 34 + ul] = hi;
                SLO[lr * 34 + ul] = lo;
            }
        }
        __syncthreads();

        // ---- coalesced writeout of h splits (+ encoder-last) ----
        __half* oHi = g_hs[outPar][0];
        __half* oLo = g_hs[outPar][1];
#pragma unroll
        for (int i = 0; i < 16; i++) {
            int f = tid + i * 256;
            int lm = f >> 5, jl = f & 31;
            int m = m0 + lm;
            size_t gidx = (size_t)m * HDIM + j0g + jl;
            __half hi = SHI[lm * 34 + jl];
            __half lo = SLO[lm * 34 + jl];
            oHi[gidx] = hi;
            oLo[gidx] = lo;
            if (!mode && t == lens[m] - 1) {
                g_eL[0][gidx] = hi;
                g_eL[1][gidx] = lo;
            }
        }
        grid_sync(sense);

        // ================= decoder fc + argmax (fused) =================
        if (mode) {
            const __half* hH = g_hs[outPar][0];
            const __half* hL = g_hs[outPar][1];
            const uint32_t fcA = sb + SM_STG;
            // stage fcA (16 rows x 256 k x 2 planes)
            {
                int p = tid >> 9, rem = tid & 511;   // 1024 jobs over 4 iters
#pragma unroll
                for (int i = 0; i < 4; i++) {
                    int f = tid + i * 256;
                    int pp = f >> 9, r2 = f & 511;
                    int row = r2 >> 5, seg = r2 & 31;
                    const __half* src = pp ? hL : hH;
                    cpa16(fcA + pp * FCA_PL_B + row * W_ROW_B + seg * 16,
                          src + (size_t)(r0fc + row) * HDIM + seg * 8);
                }
                (void)p; (void)rem;
            }
            // fcB chunk loader
            auto load_fcB = [&](int buf, int kc) {
                const int v = tid;
                const uint32_t d = sb + FCB_OFF + buf * FCB_BUF_B + v * 48;
                const size_t s = (size_t)v * HDIM + kc * 16;
                cpa16(d,                 g_fcWs[0] + s);
                cpa16(d + 16,            g_fcWs[0] + s + 8);
                cpa16(d + FCB_PL_B,      g_fcWs[1] + s);
                cpa16(d + FCB_PL_B + 16, g_fcWs[1] + s + 8);
            };
            load_fcB(0, 0); cpa_commit();

            float accF[4][4];
#pragma unroll
            for (int i = 0; i < 4; i++)
#pragma unroll
                for (int j = 0; j < 4; j++) accF[i][j] = 0.f;

            const uint32_t faOff = (uint32_t)(lane & 15) * W_ROW_B
                                   + (uint32_t)((lane >> 4) * 8) * 2;
            const int fbRow = wid * 32 + ((lane & 16) >> 1) + (lane & 7);

            for (int kc = 0; kc < 16; kc++) {
                if (kc < 15) {
                    load_fcB((kc + 1) & 1, kc + 1);
                    cpa_commit();
                    cpa_wait<1>();
                } else {
                    cpa_wait<0>();
                }
                __syncthreads();
                uint32_t fa_h[4], fa_l[4], fb_h[2][4], fb_l[2][4];
                ldsm4(fa_h, fcA + faOff + (uint32_t)(kc * 16) * 2);
                ldsm4(fa_l, fcA + FCA_PL_B + faOff + (uint32_t)(kc * 16) * 2);
                const uint32_t bufB = sb + FCB_OFF + (kc & 1) * FCB_BUF_B;
#pragma unroll
                for (int bg = 0; bg < 2; bg++) {
                    const uint32_t ro = (uint32_t)(fbRow + bg * 16) * 48
                                        + (uint32_t)bColH * 2;
                    ldsm4(fb_h[bg], bufB + ro);
                    ldsm4(fb_l[bg], bufB + FCB_PL_B + ro);
                }
#pragma unroll
                for (int nt = 0; nt < 4; nt++) {
                    const int g = nt >> 1, s = (nt & 1) * 2;
                    mma16816(accF[nt], fa_h, fb_h[g][s], fb_h[g][s + 1]);
                    mma16816(accF[nt], fa_h, fb_l[g][s], fb_l[g][s + 1]);
                    mma16816(accF[nt], fa_l, fb_h[g][s], fb_h[g][s + 1]);
                }
                __syncthreads();
            }

            // stage scores
            float* SSC = (float*)(smem + SSC_OFF);
#pragma unroll
            for (int nt = 0; nt < 4; nt++) {
                int col = wid * 32 + nt * 8 + (lane & 3) * 2;
                int r = lane >> 2;
                SSC[r * 264 + col]     = accF[nt][0];
                SSC[r * 264 + col + 1] = accF[nt][1];
                SSC[(r + 8) * 264 + col]     = accF[nt][2];
                SSC[(r + 8) * 264 + col + 1] = accF[nt][3];
            }
            __syncthreads();

            // per-row bias + out + argmax (8 warps x 2 rows)
            const float* SB = (const float*)(smem + SM_FCBIA);
#pragma unroll
            for (int rr = 0; rr < 2; rr++) {
                const int r = wid * 2 + rr;
                const int m = r0fc + r;
                float s[8];
#pragma unroll
                for (int u = 0; u < 8; u++)
                    s[u] = SSC[r * 264 + lane * 8 + u] + SB[lane * 8 + u];
                float* orow = out + (size_t)m * (TPH * VOC) + (size_t)(t - TPH) * VOC
                              + lane * 8;
                *(float4*)(orow)     = make_float4(s[0], s[1], s[2], s[3]);
                *(float4*)(orow + 4) = make_float4(s[4], s[5], s[6], s[7]);
                float bv = s[0];
                int bi = lane * 8;
#pragma unroll
                for (int u = 1; u < 8; u++)
                    if (s[u] > bv) { bv = s[u]; bi = lane * 8 + u; }
#pragma unroll
                for (int off = 16; off > 0; off >>= 1) {
                    float ov = __shfl_xor_sync(0xffffffffu, bv, off);
                    int   oi = __shfl_xor_sync(0xffffffffu, bi, off);
                    if (ov > bv || (ov == bv && oi < bi)) { bv = ov; bi = oi; }
                }
                if (lane == 0) g_tok[m] = bi;
            }
            grid_sync(sense);
        }
    }
}

// ---------------- launch ----------------
extern "C" void kernel_launch(void* const* d_in, const int* in_sizes, int n_in,
                              void* d_out, int out_size)
{
    const int*   phon   = (const int*)  d_in[0];
    const int*   plen   = (const int*)  d_in[1];
    const float* emb    = (const float*)d_in[2];
    const float* encWih = (const float*)d_in[3];
    const float* encWhh = (const float*)d_in[4];
    const float* encBih = (const float*)d_in[5];
    const float* encBhh = (const float*)d_in[6];
    const float* decWih = (const float*)d_in[7];
    const float* decWhh = (const float*)d_in[8];
    const float* decBih = (const float*)d_in[9];
    const float* decBhh = (const float*)d_in[10];
    const float* fcW    = (const float*)d_in[11];
    const float* fcb    = (const float*)d_in[12];
    const int*   sos    = (const int*)  d_in[13];
    float* out = (float*)d_out;

    cudaFuncSetAttribute(persist_kernel,
                         cudaFuncAttributeMaxDynamicSharedMemorySize, SM_TOTAL);

    split_w_kernel<<<(2 * GDIM * HDIM + 255) / 256, 256>>>(encWhh, decWhh);
    split_fc_kernel<<<(VOC * HDIM + 255) / 256, 256>>>(fcW);
    dim3 pgrid(VOC, 4, 2);
    proj_kernel<<<pgrid, 256>>>(emb, encWih, encBih, encBhh, decWih, decBih, decBhh);
    init_kernel<<<(BT * HDIM + 255) / 256, 256>>>();

    persist_kernel<<<NCTA, 256, SM_TOTAL>>>(phon, plen, fcb, sos, out);
}

// round 10
// speedup vs baseline: 1.5562x; 1.0092x over previous
#include <cuda_runtime.h>
#include <cuda_fp16.h>
#include <stdint.h>

#define BT   2048
#define TPH  32
#define EDIM 128
#define HDIM 256
#define GDIM 1024
#define VOC  256

#define NCTA 128          // 16 m-blocks x 8 n-blocks, 1 CTA/SM (co-resident)
#define MT   128
#define NTP  128          // n' (gate-interleaved) per CTA

// ---------------- smem map (bytes) ----------------
#define W_ROW_B   528                    // 256 halfs + 8 pad
#define W_PLANE_B (128 * W_ROW_B)        // 67584
#define SM_W      0
#define SM_STG    (2 * W_PLANE_B)        // 135168
#define SM_STG_B  66560
// LSTM A stages: 3 x 20480 (chunk = 2 planes x 128 rows x 80B)
#define A_PL_B    10240
#define A_CH_B    20480
// fc: fcA 2x8448 @SM_STG ; fcB 2 bufs x 24576 after
#define FCA_PL_B  8448
#define FCB_OFF   (SM_STG + 16896)
#define FCB_BUF_B 24576
#define FCB_PL_B  12288
#define SSC_OFF   (SM_STG + 16896)       // scores 16x264 f32 (after fc GEMM)
// epilogue h staging (overlays stage region)
#define SHI_OFF   SM_STG
#define SLO_OFF   (SM_STG + 8704)        // 128*68
#define SM_FCBIA  (SM_STG + SM_STG_B)    // 256 f32 bias
#define SM_TOTAL  (SM_FCBIA + 1024)      // 202752

// ---------------- device scratch ----------------
__device__ float   g_projP[2][VOC * GDIM];
__device__ __half  g_Ws[2][2][GDIM * HDIM];    // Whh splits, gate-interleaved
__device__ __half  g_fcWs[2][VOC * HDIM];      // fcW splits, v-major
__device__ __half  g_hs[2][2][BT * HDIM];      // h splits by parity
__device__ __half  g_eL[2][BT * HDIM];
__device__ int     g_tok[BT];
__device__ unsigned          g_bar_cnt = 0;
__device__ volatile unsigned g_bar_sense = 0;

// ---------------- fast pointwise ----------------
__device__ __forceinline__ float fast_sigmoid(float x) {
    return __fdividef(1.f, 1.f + __expf(-x));
}
__device__ __forceinline__ float fast_tanh(float x) {
    return 1.f - __fdividef(2.f, __expf(2.f * x) + 1.f);
}

// ---------------- PTX helpers ----------------
__device__ __forceinline__ uint32_t smem_u32(const void* p) {
    uint32_t a;
    asm("{ .reg .u64 t; cvta.to.shared.u64 t, %1; cvt.u32.u64 %0, t; }" : "=r"(a) : "l"(p));
    return a;
}
__device__ __forceinline__ void cpa16(uint32_t saddr, const void* g) {
    asm volatile("cp.async.cg.shared.global [%0], [%1], 16;" :: "r"(saddr), "l"(g));
}
__device__ __forceinline__ void cpa_commit() {
    asm volatile("cp.async.commit_group;" ::: "memory");
}
template <int N>
__device__ __forceinline__ void cpa_wait() {
    asm volatile("cp.async.wait_group %0;" :: "n"(N) : "memory");
}
__device__ __forceinline__ void ldsm4(uint32_t* r, uint32_t addr) {
    asm volatile("ldmatrix.sync.aligned.m8n8.x4.shared.b16 {%0,%1,%2,%3}, [%4];"
        : "=r"(r[0]), "=r"(r[1]), "=r"(r[2]), "=r"(r[3]) : "r"(addr));
}
__device__ __forceinline__ void mma16816(float* c, const uint32_t* a,
                                         uint32_t b0, uint32_t b1) {
    asm volatile("mma.sync.aligned.m16n8k16.row.col.f32.f16.f16.f32 "
        "{%0,%1,%2,%3}, {%4,%5,%6,%7}, {%8,%9}, {%0,%1,%2,%3};"
        : "+f"(c[0]), "+f"(c[1]), "+f"(c[2]), "+f"(c[3])
        : "r"(a[0]), "r"(a[1]), "r"(a[2]), "r"(a[3]), "r"(b0), "r"(b1));
}

// ---------------- grid barrier (sense-reversing; even flips per launch) -----
__device__ __forceinline__ void grid_sync(unsigned& sense) {
    sense ^= 1u;
    __syncthreads();
    if (threadIdx.x == 0) {
        __threadfence();
        if (atomicAdd(&g_bar_cnt, 1u) == NCTA - 1) {
            g_bar_cnt = 0;
            __threadfence();
            g_bar_sense = sense;
        } else {
            while (g_bar_sense != sense) __nanosleep(32);
        }
        __threadfence();
    }
    __syncthreads();
}

// ---------------- prep kernels ----------------
__global__ void split_w_kernel(const float* __restrict__ Wenc,
                               const float* __restrict__ Wdec)
{
    int gidx = blockIdx.x * blockDim.x + threadIdx.x;
    if (gidx >= 2 * GDIM * HDIM) return;
    int which = gidx >= GDIM * HDIM;
    int idx = gidx - which * (GDIM * HDIM);
    const float* W = which ? Wdec : Wenc;
    int np = idx >> 8, k = idx & 255;
    int j = np >> 2, g = np & 3;
    float w = W[(size_t)(g * HDIM + j) * HDIM + k];
    __half hi = __float2half_rn(w);
    __half lo = __float2half_rn(w - __half2float(hi));
    g_Ws[which][0][idx] = hi;
    g_Ws[which][1][idx] = lo;
}

__global__ void split_fc_kernel(const float* __restrict__ fcW)
{
    int idx = blockIdx.x * blockDim.x + threadIdx.x;
    if (idx >= VOC * HDIM) return;
    float w = fcW[idx];
    __half hi = __float2half_rn(w);
    __half lo = __float2half_rn(w - __half2float(hi));
    g_fcWs[0][idx] = hi;
    g_fcWs[1][idx] = lo;
}

__global__ void proj_kernel(const float* __restrict__ emb,
                            const float* __restrict__ Wenc,
                            const float* __restrict__ b1e,
                            const float* __restrict__ b2e,
                            const float* __restrict__ Wdec,
                            const float* __restrict__ b1d,
                            const float* __restrict__ b2d)
{
    int which = blockIdx.z;
    const float* W  = which ? Wdec : Wenc;
    const float* b1 = which ? b1d : b1e;
    const float* b2 = which ? b2d : b2e;
    int v = blockIdx.x;
    __shared__ float es[EDIM];
    int tid = threadIdx.x;
    if (tid < EDIM) es[tid] = emb[v * EDIM + tid];
    __syncthreads();
    int n = blockIdx.y * 256 + tid;
    const float4* wr = (const float4*)(W + (size_t)n * EDIM);
    float a0 = 0.f, a1 = 0.f, a2 = 0.f, a3 = 0.f;
#pragma unroll
    for (int k4 = 0; k4 < EDIM / 16; k4++) {
        float4 w0 = wr[k4 * 4 + 0];
        float4 w1 = wr[k4 * 4 + 1];
        float4 w2 = wr[k4 * 4 + 2];
        float4 w3 = wr[k4 * 4 + 3];
        const float* e = es + k4 * 16;
        a0 += e[0] * w0.x + e[1] * w0.y + e[2] * w0.z + e[3] * w0.w;
        a1 += e[4] * w1.x + e[5] * w1.y + e[6] * w1.z + e[7] * w1.w;
        a2 += e[8] * w2.x + e[9] * w2.y + e[10] * w2.z + e[11] * w2.w;
        a3 += e[12] * w3.x + e[13] * w3.y + e[14] * w3.z + e[15] * w3.w;
    }
    int np = (n & 255) * 4 + (n >> 8);
    g_projP[which][(size_t)v * GDIM + np] = (a0 + a1) + (a2 + a3) + b1[n] + b2[n];
}

__global__ void init_kernel()
{
    int i = blockIdx.x * blockDim.x + threadIdx.x;
    if (i < BT * HDIM) {
        __half z = __float2half_rn(0.f);
        g_hs[0][0][i] = z; g_hs[0][1][i] = z;
    }
}

// ---------------- persistent kernel ----------------
__global__ void __launch_bounds__(256, 1)
persist_kernel(const int* __restrict__ phon, const int* __restrict__ lens,
               const float* __restrict__ fcb, const int* __restrict__ sos,
               float* __restrict__ out)
{
    extern __shared__ char smem[];
    const uint32_t sb = smem_u32(smem);

    const int tid  = threadIdx.x;
    const int lane = tid & 31;
    const int wid  = tid >> 5;
    const int wm = wid & 1, wn = wid >> 1;
    const int bm = blockIdx.x >> 3, bn = blockIdx.x & 7;
    const int m0 = bm * MT;
    const int n0 = bn * NTP;
    const int j0g = bn * 32;
    const int r0fc = blockIdx.x * 16;

    unsigned sense = 0;
    const int sos0 = sos[0];

    // fc bias into smem
    ((float*)(smem + SM_FCBIA))[tid] = fcb[tid];

    // fragment / epilogue ownership
    const int aRow = wm * 64 + (lane & 15);
    const int aCol = (lane >> 4) * 8;
    const int bRow = wn * 32 + ((lane & 16) >> 1) + (lane & 7);
    const int bColH = ((lane >> 3) & 1) * 8;
    const int myRow = wm * 64 + (lane >> 2) + (lane & 1) * 8;
    const int myUlB = wn * 8 + ((lane & 2) >> 1);
    const bool odd = (lane & 1);

    // resident W loader (mode)
    auto load_W = [&](int mode) {
        for (int f = tid; f < 8192; f += 256) {
            int p = f >> 12, rem = f & 4095;
            int row = rem >> 5, seg = rem & 31;
            cpa16(sb + SM_W + p * W_PLANE_B + row * W_ROW_B + seg * 16,
                  g_Ws[mode][p] + (size_t)(n0 + row) * HDIM + seg * 8);
        }
        cpa_commit();
        cpa_wait<0>();
        __syncthreads();
    };
    load_W(0);

    // per-thread persistent c
    float cpre[4][4];
#pragma unroll
    for (int i = 0; i < 4; i++)
#pragma unroll
        for (int j = 0; j < 4; j++) cpre[i][j] = 0.f;

    // encoder lens preload (for eL condition in writeout we read global)
    for (int t = 0; t < 2 * TPH; t++) {
        const int mode = (t >= TPH);
        if (t == TPH) {
            load_W(1);
#pragma unroll
            for (int i = 0; i < 4; i++)
#pragma unroll
                for (int j = 0; j < 4; j++) cpre[i][j] = 0.f;
        }
        const int inPar = t & 1, outPar = inPar ^ 1;
        const __half* A0 = (t == TPH) ? g_eL[0] : g_hs[inPar][0];
        const __half* A1 = (t == TPH) ? g_eL[1] : g_hs[inPar][1];

        // prefetch tokens (available since last barrier)
        int tokr[4];
#pragma unroll
        for (int mt = 0; mt < 4; mt++) {
            const int m = m0 + myRow + mt * 16;
            tokr[mt] = mode ? ((t == TPH) ? sos0 : g_tok[m]) : phon[m * TPH + t];
        }

        float acc[4][4][4];
#pragma unroll
        for (int i = 0; i < 4; i++)
#pragma unroll
            for (int j = 0; j < 4; j++)
#pragma unroll
                for (int q = 0; q < 4; q++) acc[i][j][q] = 0.f;

        // A chunk loader
        auto load_a = [&](int stg, int kb) {
            const int row = tid >> 1;
            const int half = tid & 1;
            const uint32_t d0 = sb + SM_STG + stg * A_CH_B + row * 80 + half * 32;
            const size_t s0 = (size_t)(m0 + row) * HDIM + kb * 32 + half * 16;
            cpa16(d0,                    A0 + s0);
            cpa16(d0 + 16,               A0 + s0 + 8);
            cpa16(d0 + A_PL_B,           A1 + s0);
            cpa16(d0 + A_PL_B + 16,      A1 + s0 + 8);
        };

        load_a(0, 0); cpa_commit();
        load_a(1, 1); cpa_commit();

        for (int kb = 0; kb < 8; kb++) {
            if (kb < 6) {
                load_a((kb + 2) % 3, kb + 2);
                cpa_commit();
                cpa_wait<2>();
            } else if (kb == 6) {
                cpa_wait<1>();
            } else {
                cpa_wait<0>();
            }
            __syncthreads();

            const uint32_t bA = sb + SM_STG + (kb % 3) * A_CH_B;
#pragma unroll
            for (int k16 = 0; k16 < 2; k16++) {
                const uint32_t aOff = (uint32_t)(k16 * 16 + aCol) * 2;
                const uint32_t kW = (uint32_t)(kb * 32 + k16 * 16 + bColH) * 2;
                uint32_t ah[4][4], al[4][4], bh[2][4], bl[2][4];
#pragma unroll
                for (int mt = 0; mt < 4; mt++) {
                    ldsm4(ah[mt], bA + (uint32_t)(aRow + mt * 16) * 80 + aOff);
                    ldsm4(al[mt], bA + A_PL_B + (uint32_t)(aRow + mt * 16) * 80 + aOff);
                }
#pragma unroll
                for (int bg = 0; bg < 2; bg++) {
                    ldsm4(bh[bg], sb + SM_W + (uint32_t)(bRow + bg * 16) * W_ROW_B + kW);
                    ldsm4(bl[bg], sb + SM_W + W_PLANE_B
                                   + (uint32_t)(bRow + bg * 16) * W_ROW_B + kW);
                }
#pragma unroll
                for (int mt = 0; mt < 4; mt++)
#pragma unroll
                    for (int nt = 0; nt < 4; nt++) {
                        const int g = nt >> 1, s = (nt & 1) * 2;
                        mma16816(acc[mt][nt], ah[mt], bh[g][s], bh[g][s + 1]);
                    }
#pragma unroll
                for (int mt = 0; mt < 4; mt++)
#pragma unroll
                    for (int nt = 0; nt < 4; nt++) {
                        const int g = nt >> 1, s = (nt & 1) * 2;
                        mma16816(acc[mt][nt], ah[mt], bl[g][s], bl[g][s + 1]);
                    }
#pragma unroll
                for (int mt = 0; mt < 4; mt++)
#pragma unroll
                    for (int nt = 0; nt < 4; nt++) {
                        const int g = nt >> 1, s = (nt & 1) * 2;
                        mma16816(acc[mt][nt], al[mt], bh[g][s], bh[g][s + 1]);
                    }
            }
            __syncthreads();
        }

        // ---- epilogue: shuffle gates, activations, c in regs ----
        __half* SHI = (__half*)(smem + SHI_OFF);
        __half* SLO = (__half*)(smem + SLO_OFF);
        const float* projT = g_projP[mode];
#pragma unroll
        for (int mt = 0; mt < 4; mt++) {
#pragma unroll
            for (int nt = 0; nt < 4; nt++) {
                const int ul = myUlB + nt * 2;
                const float4 p = *(const float4*)&projT[(size_t)tokr[mt] * GDIM
                                                        + n0 + ul * 4];
                float c0 = acc[mt][nt][0], c1 = acc[mt][nt][1];
                float c2 = acc[mt][nt][2], c3 = acc[mt][nt][3];
                float sA = odd ? c0 : c2;
                float sB = odd ? c1 : c3;
                float rA = __shfl_xor_sync(0xffffffffu, sA, 1);
                float rB = __shfl_xor_sync(0xffffffffu, sB, 1);
                float gi = odd ? rA : c0;
                float gf = odd ? rB : c1;
                float gg = odd ? c2 : rA;
                float go = odd ? c3 : rB;
                float iv = fast_sigmoid(gi + p.x);
                float fv = fast_sigmoid(gf + p.y);
                float gv = fast_tanh(gg + p.z);
                float ov = fast_sigmoid(go + p.w);
                float cn = fv * cpre[mt][nt] + iv * gv;
                cpre[mt][nt] = cn;
                float hv = ov * fast_tanh(cn);
                __half hi = __float2half_rn(hv);
                __half lo = __float2half_rn(hv - __half2float(hi));
                const int lr = myRow + mt * 16;
                SHI[lr * 34 + ul] = hi;
                SLO[lr * 34 + ul] = lo;
            }
        }
        __syncthreads();

        // ---- coalesced writeout of h splits (+ encoder-last) ----
        __half* oHi = g_hs[outPar][0];
        __half* oLo = g_hs[outPar][1];
#pragma unroll
        for (int i = 0; i < 16; i++) {
            int f = tid + i * 256;
            int lm = f >> 5, jl = f & 31;
            int m = m0 + lm;
            size_t gidx = (size_t)m * HDIM + j0g + jl;
            __half hi = SHI[lm * 34 + jl];
            __half lo = SLO[lm * 34 + jl];
            oHi[gidx] = hi;
            oLo[gidx] = lo;
            if (!mode && t == lens[m] - 1) {
                g_eL[0][gidx] = hi;
                g_eL[1][gidx] = lo;
            }
        }
        grid_sync(sense);

        // ================= decoder fc + argmax (fused) =================
        if (mode) {
            const __half* hH = g_hs[outPar][0];
            const __half* hL = g_hs[outPar][1];
            const uint32_t fcA = sb + SM_STG;
            // stage fcA (16 rows x 256 k x 2 planes)
            {
                int p = tid >> 9, rem = tid & 511;   // 1024 jobs over 4 iters
#pragma unroll
                for (int i = 0; i < 4; i++) {
                    int f = tid + i * 256;
                    int pp = f >> 9, r2 = f & 511;
                    int row = r2 >> 5, seg = r2 & 31;
                    const __half* src = pp ? hL : hH;
                    cpa16(fcA + pp * FCA_PL_B + row * W_ROW_B + seg * 16,
                          src + (size_t)(r0fc + row) * HDIM + seg * 8);
                }
                (void)p; (void)rem;
            }
            // fcB chunk loader
            auto load_fcB = [&](int buf, int kc) {
                const int v = tid;
                const uint32_t d = sb + FCB_OFF + buf * FCB_BUF_B + v * 48;
                const size_t s = (size_t)v * HDIM + kc * 16;
                cpa16(d,                 g_fcWs[0] + s);
                cpa16(d + 16,            g_fcWs[0] + s + 8);
                cpa16(d + FCB_PL_B,      g_fcWs[1] + s);
                cpa16(d + FCB_PL_B + 16, g_fcWs[1] + s + 8);
            };
            load_fcB(0, 0); cpa_commit();

            float accF[4][4];
#pragma unroll
            for (int i = 0; i < 4; i++)
#pragma unroll
                for (int j = 0; j < 4; j++) accF[i][j] = 0.f;

            const uint32_t faOff = (uint32_t)(lane & 15) * W_ROW_B
                                   + (uint32_t)((lane >> 4) * 8) * 2;
            const int fbRow = wid * 32 + ((lane & 16) >> 1) + (lane & 7);

            for (int kc = 0; kc < 16; kc++) {
                if (kc < 15) {
                    load_fcB((kc + 1) & 1, kc + 1);
                    cpa_commit();
                    cpa_wait<1>();
                } else {
                    cpa_wait<0>();
                }
                __syncthreads();
                uint32_t fa_h[4], fa_l[4], fb_h[2][4], fb_l[2][4];
                ldsm4(fa_h, fcA + faOff + (uint32_t)(kc * 16) * 2);
                ldsm4(fa_l, fcA + FCA_PL_B + faOff + (uint32_t)(kc * 16) * 2);
                const uint32_t bufB = sb + FCB_OFF + (kc & 1) * FCB_BUF_B;
#pragma unroll
                for (int bg = 0; bg < 2; bg++) {
                    const uint32_t ro = (uint32_t)(fbRow + bg * 16) * 48
                                        + (uint32_t)bColH * 2;
                    ldsm4(fb_h[bg], bufB + ro);
                    ldsm4(fb_l[bg], bufB + FCB_PL_B + ro);
                }
#pragma unroll
                for (int nt = 0; nt < 4; nt++) {
                    const int g = nt >> 1, s = (nt & 1) * 2;
                    mma16816(accF[nt], fa_h, fb_h[g][s], fb_h[g][s + 1]);
                    mma16816(accF[nt], fa_h, fb_l[g][s], fb_l[g][s + 1]);
                    mma16816(accF[nt], fa_l, fb_h[g][s], fb_h[g][s + 1]);
                }
                __syncthreads();
            }

            // stage scores
            float* SSC = (float*)(smem + SSC_OFF);
#pragma unroll
            for (int nt = 0; nt < 4; nt++) {
                int col = wid * 32 + nt * 8 + (lane & 3) * 2;
                int r = lane >> 2;
                SSC[r * 264 + col]     = accF[nt][0];
                SSC[r * 264 + col + 1] = accF[nt][1];
                SSC[(r + 8) * 264 + col]     = accF[nt][2];
                SSC[(r + 8) * 264 + col + 1] = accF[nt][3];
            }
            __syncthreads();

            // per-row bias + out + argmax (8 warps x 2 rows)
            const float* SB = (const float*)(smem + SM_FCBIA);
#pragma unroll
            for (int rr = 0; rr < 2; rr++) {
                const int r = wid * 2 + rr;
                const int m = r0fc + r;
                float s[8];
#pragma unroll
                for (int u = 0; u < 8; u++)
                    s[u] = SSC[r * 264 + lane * 8 + u] + SB[lane * 8 + u];
                float* orow = out + (size_t)m * (TPH * VOC) + (size_t)(t - TPH) * VOC
                              + lane * 8;
                *(float4*)(orow)     = make_float4(s[0], s[1], s[2], s[3]);
                *(float4*)(orow + 4) = make_float4(s[4], s[5], s[6], s[7]);
                float bv = s[0];
                int bi = lane * 8;
#pragma unroll
                for (int u = 1; u < 8; u++)
                    if (s[u] > bv) { bv = s[u]; bi = lane * 8 + u; }
#pragma unroll
                for (int off = 16; off > 0; off >>= 1) {
                    float ov = __shfl_xor_sync(0xffffffffu, bv, off);
                    int   oi = __shfl_xor_sync(0xffffffffu, bi, off);
                    if (ov > bv || (ov == bv && oi < bi)) { bv = ov; bi = oi; }
                }
                if (lane == 0) g_tok[m] = bi;
            }
            grid_sync(sense);
        }
    }
}

// ---------------- launch ----------------
extern "C" void kernel_launch(void* const* d_in, const int* in_sizes, int n_in,
                              void* d_out, int out_size)
{
    const int*   phon   = (const int*)  d_in[0];
    const int*   plen   = (const int*)  d_in[1];
    const float* emb    = (const float*)d_in[2];
    const float* encWih = (const float*)d_in[3];
    const float* encWhh = (const float*)d_in[4];
    const float* encBih = (const float*)d_in[5];
    const float* encBhh = (const float*)d_in[6];
    const float* decWih = (const float*)d_in[7];
    const float* decWhh = (const float*)d_in[8];
    const float* decBih = (const float*)d_in[9];
    const float* decBhh = (const float*)d_in[10];
    const float* fcW    = (const float*)d_in[11];
    const float* fcb    = (const float*)d_in[12];
    const int*   sos    = (const int*)  d_in[13];
    float* out = (float*)d_out;

    cudaFuncSetAttribute(persist_kernel,
                         cudaFuncAttributeMaxDynamicSharedMemorySize, SM_TOTAL);

    split_w_kernel<<<(2 * GDIM * HDIM + 255) / 256, 256>>>(encWhh, decWhh);
    split_fc_kernel<<<(VOC * HDIM + 255) / 256, 256>>>(fcW);
    dim3 pgrid(VOC, 4, 2);
    proj_kernel<<<pgrid, 256>>>(emb, encWih, encBih, encBhh, decWih, decBih, decBhh);
    init_kernel<<<(BT * HDIM + 255) / 256, 256>>>();

    persist_kernel<<<NCTA, 256, SM_TOTAL>>>(phon, plen, fcb, sos, out);
}

// round 11
// speedup vs baseline: 1.7598x; 1.1308x over previous
#include <cuda_runtime.h>
#include <cuda_fp16.h>
#include <stdint.h>

#define BT   2048
#define TPH  32
#define EDIM 128
#define HDIM 256
#define GDIM 1024
#define VOC  256

#define NCTA 128
#define MT   128
#define NTP  128

// ---------------- smem map (bytes) ----------------
#define W_ROW_B   528
#define W_PLANE_B (128 * W_ROW_B)        // 67584
#define SM_W      0
#define FCW_PL_B  (32 * W_ROW_B)         // 16896
#define SM_FCW    (2 * W_PLANE_B)        // 135168
#define SM_STG    (SM_FCW + 2 * FCW_PL_B) // 168960
#define A_PL_B    10240                  // 128 rows x 80 B
#define A_CH_B    20480
#define SM_BIAS   (SM_STG + 3 * A_CH_B)  // 230400 (32 f32)
#define SM_TOK    (SM_BIAS + 128)        // 230528 (128 i32: SLEN in enc / STOK in dec)
#define SM_TOTAL  (SM_TOK + 512)         // 231040  (< 232448 max)

// overlays inside stage region (valid when stages idle)
#define SHI_OFF   SM_STG                 // 128*34 halfs
#define SLO_OFF   (SM_STG + 8704)
#define SSC_OFF   SM_STG                 // 128*33 f32
#define PV_OFF    SM_STG                 // 8*128 f32
#define PI_OFF    (SM_STG + 4096)        // 8*128 i32

// ---------------- device scratch ----------------
__device__ float   g_projP[2][VOC * GDIM];
__device__ __half  g_Ws[2][2][GDIM * HDIM];
__device__ __half  g_fcWs[2][VOC * HDIM];
__device__ __half  g_hs[2][2][BT * HDIM];
__device__ __half  g_eL[2][BT * HDIM];
__device__ float   g_pval[8][BT];
__device__ int     g_pidx[8][BT];
__device__ unsigned          g_bar_cnt = 0;
__device__ volatile unsigned g_bar_sense = 0;

// ---------------- fast pointwise ----------------
__device__ __forceinline__ float fast_sigmoid(float x) {
    return __fdividef(1.f, 1.f + __expf(-x));
}
__device__ __forceinline__ float fast_tanh(float x) {
    return 1.f - __fdividef(2.f, __expf(2.f * x) + 1.f);
}

// ---------------- PTX helpers ----------------
__device__ __forceinline__ uint32_t smem_u32(const void* p) {
    uint32_t a;
    asm("{ .reg .u64 t; cvta.to.shared.u64 t, %1; cvt.u32.u64 %0, t; }" : "=r"(a) : "l"(p));
    return a;
}
__device__ __forceinline__ void cpa16(uint32_t saddr, const void* g) {
    asm volatile("cp.async.cg.shared.global [%0], [%1], 16;" :: "r"(saddr), "l"(g));
}
__device__ __forceinline__ void cpa_commit() {
    asm volatile("cp.async.commit_group;" ::: "memory");
}
template <int N>
__device__ __forceinline__ void cpa_wait() {
    asm volatile("cp.async.wait_group %0;" :: "n"(N) : "memory");
}
__device__ __forceinline__ void ldsm4(uint32_t* r, uint32_t addr) {
    asm volatile("ldmatrix.sync.aligned.m8n8.x4.shared.b16 {%0,%1,%2,%3}, [%4];"
        : "=r"(r[0]), "=r"(r[1]), "=r"(r[2]), "=r"(r[3]) : "r"(addr));
}
__device__ __forceinline__ void ldsm2(uint32_t* r, uint32_t addr) {
    asm volatile("ldmatrix.sync.aligned.m8n8.x2.shared.b16 {%0,%1}, [%2];"
        : "=r"(r[0]), "=r"(r[1]) : "r"(addr));
}
__device__ __forceinline__ void mma16816(float* c, const uint32_t* a,
                                         uint32_t b0, uint32_t b1) {
    asm volatile("mma.sync.aligned.m16n8k16.row.col.f32.f16.f16.f32 "
        "{%0,%1,%2,%3}, {%4,%5,%6,%7}, {%8,%9}, {%0,%1,%2,%3};"
        : "+f"(c[0]), "+f"(c[1]), "+f"(c[2]), "+f"(c[3])
        : "r"(a[0]), "r"(a[1]), "r"(a[2]), "r"(a[3]), "r"(b0), "r"(b1));
}

// ---------------- grid barrier ----------------
__device__ __forceinline__ void grid_sync(unsigned& sense) {
    sense ^= 1u;
    __syncthreads();
    if (threadIdx.x == 0) {
        __threadfence();
        if (atomicAdd(&g_bar_cnt, 1u) == NCTA - 1) {
            g_bar_cnt = 0;
            __threadfence();
            g_bar_sense = sense;
        } else {
            while (g_bar_sense != sense) __nanosleep(32);
        }
        __threadfence();
    }
    __syncthreads();
}

// ---------------- merged prep (one launch) ----------------
// blocks [0,2048): split Whh   [2048,2304): split fcW
// blocks [2304,4352): init h   [4352,6400): proj tables
__global__ void prep_kernel(const float* __restrict__ Wenc,
                            const float* __restrict__ Wdec,
                            const float* __restrict__ fcW,
                            const float* __restrict__ emb,
                            const float* __restrict__ eWih,
                            const float* __restrict__ eB1,
                            const float* __restrict__ eB2,
                            const float* __restrict__ dWih,
                            const float* __restrict__ dB1,
                            const float* __restrict__ dB2)
{
    __shared__ float es[EDIM];
    const int bid = blockIdx.x;
    const int tid = threadIdx.x;
    if (bid < 2048) {
        int gidx = bid * 256 + tid;
        int which = gidx >= GDIM * HDIM;
        int idx = gidx - which * (GDIM * HDIM);
        const float* W = which ? Wdec : Wenc;
        int np = idx >> 8, k = idx & 255;
        int j = np >> 2, g = np & 3;
        float w = W[(size_t)(g * HDIM + j) * HDIM + k];
        __half hi = __float2half_rn(w);
        __half lo = __float2half_rn(w - __half2float(hi));
        g_Ws[which][0][idx] = hi;
        g_Ws[which][1][idx] = lo;
    } else if (bid < 2304) {
        int idx = (bid - 2048) * 256 + tid;
        float w = fcW[idx];
        __half hi = __float2half_rn(w);
        __half lo = __float2half_rn(w - __half2float(hi));
        g_fcWs[0][idx] = hi;
        g_fcWs[1][idx] = lo;
    } else if (bid < 4352) {
        int i = (bid - 2304) * 256 + tid;
        __half z = __float2half_rn(0.f);
        g_hs[0][0][i] = z; g_hs[0][1][i] = z;
    } else {
        int pb = bid - 4352;
        int v = pb >> 3, sub = pb & 7;
        int which = sub >> 2, ny = sub & 3;
        const float* W  = which ? dWih : eWih;
        const float* b1 = which ? dB1 : eB1;
        const float* b2 = which ? dB2 : eB2;
        if (tid < EDIM) es[tid] = emb[v * EDIM + tid];
        __syncthreads();
        int n = ny * 256 + tid;
        const float4* wr = (const float4*)(W + (size_t)n * EDIM);
        float a0 = 0.f, a1 = 0.f, a2 = 0.f, a3 = 0.f;
#pragma unroll
        for (int k4 = 0; k4 < EDIM / 16; k4++) {
            float4 w0 = wr[k4 * 4 + 0];
            float4 w1 = wr[k4 * 4 + 1];
            float4 w2 = wr[k4 * 4 + 2];
            float4 w3 = wr[k4 * 4 + 3];
            const float* e = es + k4 * 16;
            a0 += e[0] * w0.x + e[1] * w0.y + e[2] * w0.z + e[3] * w0.w;
            a1 += e[4] * w1.x + e[5] * w1.y + e[6] * w1.z + e[7] * w1.w;
            a2 += e[8] * w2.x + e[9] * w2.y + e[10] * w2.z + e[11] * w2.w;
            a3 += e[12] * w3.x + e[13] * w3.y + e[14] * w3.z + e[15] * w3.w;
        }
        int np = (n & 255) * 4 + (n >> 8);
        g_projP[which][(size_t)v * GDIM + np] = (a0 + a1) + (a2 + a3) + b1[n] + b2[n];
    }
}

// ---------------- A-chunk loader (h splits, k=32) ----------------
__device__ __forceinline__ void load_chunk(uint32_t dst, const __half* __restrict__ A0,
                                           const __half* __restrict__ A1,
                                           int m0, int kb, int tid)
{
    const int row = tid >> 1;
    const int half = tid & 1;
    const uint32_t d0 = dst + (uint32_t)(row * 80 + half * 32);
    const size_t s0 = (size_t)(m0 + row) * HDIM + kb * 32 + half * 16;
    cpa16(d0,               A0 + s0);
    cpa16(d0 + 16,          A0 + s0 + 8);
    cpa16(d0 + A_PL_B,      A1 + s0);
    cpa16(d0 + A_PL_B + 16, A1 + s0 + 8);
}

// ---------------- persistent kernel ----------------
__global__ void __launch_bounds__(256, 1)
persist_kernel(const int* __restrict__ phon, const int* __restrict__ lens,
               const float* __restrict__ fcb, const int* __restrict__ sos,
               float* __restrict__ out)
{
    extern __shared__ char smem[];
    const uint32_t sb = smem_u32(smem);

    const int tid  = threadIdx.x;
    const int lane = tid & 31;
    const int wid  = tid >> 5;
    const int wm = wid & 1, wn = wid >> 1;
    const int bm = blockIdx.x >> 3, bn = blockIdx.x & 7;
    const int m0 = bm * MT;
    const int n0 = bn * NTP;
    const int j0g = bn * 32;

    unsigned sense = 0;
    const int sos0 = sos[0];

    if (tid < 32) ((float*)(smem + SM_BIAS))[tid] = fcb[bn * 32 + tid];
    if (tid < 128) ((int*)(smem + SM_TOK))[tid] = lens[m0 + tid];  // SLEN (enc phase)

    const int aRow = wm * 64 + (lane & 15);
    const int aCol = (lane >> 4) * 8;
    const int bRow = wn * 32 + ((lane & 16) >> 1) + (lane & 7);
    const int bColH = ((lane >> 3) & 1) * 8;
    const int myRow = wm * 64 + (lane >> 2) + (lane & 1) * 8;
    const int myUlB = wn * 8 + ((lane & 2) >> 1);
    const bool odd = (lane & 1);

    // resident W loader; also stages the fcW slice when entering decoder
    auto load_W = [&](int mode) {
        for (int f = tid; f < 8192; f += 256) {
            int p = f >> 12, rem = f & 4095;
            int row = rem >> 5, seg = rem & 31;
            cpa16(sb + SM_W + p * W_PLANE_B + row * W_ROW_B + seg * 16,
                  g_Ws[mode][p] + (size_t)(n0 + row) * HDIM + seg * 8);
        }
        if (mode) {
            for (int f = tid; f < 2048; f += 256) {
                int p = f >> 10, rem = f & 1023;
                int row = rem >> 5, seg = rem & 31;
                cpa16(sb + SM_FCW + p * FCW_PL_B + row * W_ROW_B + seg * 16,
                      g_fcWs[p] + (size_t)(bn * 32 + row) * HDIM + seg * 8);
            }
        }
        cpa_commit();
        cpa_wait<0>();
        __syncthreads();
    };
    load_W(0);

    float cpre[4][4];
#pragma unroll
    for (int i = 0; i < 4; i++)
#pragma unroll
        for (int j = 0; j < 4; j++) cpre[i][j] = 0.f;

    for (int t = 0; t < 2 * TPH; t++) {
        const int mode = (t >= TPH);
        if (t == TPH) {
            load_W(1);
#pragma unroll
            for (int i = 0; i < 4; i++)
#pragma unroll
                for (int j = 0; j < 4; j++) cpre[i][j] = 0.f;
        }
        const int inPar = t & 1, outPar = inPar ^ 1;
        const __half* A0 = (t == TPH) ? g_eL[0] : g_hs[inPar][0];
        const __half* A1 = (t == TPH) ? g_eL[1] : g_hs[inPar][1];

        // ---- token resolution ----
        int tokr[4];
        if (!mode) {
#pragma unroll
            for (int mt = 0; mt < 4; mt++)
                tokr[mt] = phon[(m0 + myRow + mt * 16) * TPH + t];
        } else if (t == TPH) {
#pragma unroll
            for (int mt = 0; mt < 4; mt++) tokr[mt] = sos0;
        } else {
            // reduce fc partials (8 slices) cooperatively
            float* PV = (float*)(smem + PV_OFF);
            int*   PI = (int*)(smem + PI_OFF);
#pragma unroll
            for (int i = 0; i < 4; i++) {
                int f = tid + i * 256;
                int bnp = f >> 7, lm = f & 127;
                PV[f] = g_pval[bnp][m0 + lm];
                PI[f] = g_pidx[bnp][m0 + lm];
            }
            __syncthreads();
            int* STOK = (int*)(smem + SM_TOK);
            if (tid < 128) {
                float bv = PV[tid];
                int   bi = PI[tid];
#pragma unroll
                for (int b = 1; b < 8; b++) {
                    float ov = PV[b * 128 + tid];
                    int   oi = PI[b * 128 + tid];
                    if (ov > bv || (ov == bv && oi < bi)) { bv = ov; bi = oi; }
                }
                STOK[tid] = bi;
            }
            __syncthreads();
#pragma unroll
            for (int mt = 0; mt < 4; mt++)
                tokr[mt] = STOK[myRow + mt * 16];
        }

        float acc[4][4][4];
#pragma unroll
        for (int i = 0; i < 4; i++)
#pragma unroll
            for (int j = 0; j < 4; j++)
#pragma unroll
                for (int q = 0; q < 4; q++) acc[i][j][q] = 0.f;

        load_chunk(sb + SM_STG, A0, A1, m0, 0, tid); cpa_commit();
        load_chunk(sb + SM_STG + A_CH_B, A0, A1, m0, 1, tid); cpa_commit();

        for (int kb = 0; kb < 8; kb++) {
            if (kb < 7) cpa_wait<1>(); else cpa_wait<0>();
            __syncthreads();
            if (kb < 6) {
                load_chunk(sb + SM_STG + ((kb + 2) % 3) * A_CH_B, A0, A1, m0, kb + 2, tid);
                cpa_commit();
            }
            const uint32_t bA = sb + SM_STG + (kb % 3) * A_CH_B;
#pragma unroll
            for (int k16 = 0; k16 < 2; k16++) {
                const uint32_t aOff = (uint32_t)(k16 * 16 + aCol) * 2;
                const uint32_t kW = (uint32_t)(kb * 32 + k16 * 16 + bColH) * 2;
                uint32_t ah[4][4], al[4][4], bh[2][4], bl[2][4];
#pragma unroll
                for (int mt = 0; mt < 4; mt++) {
                    ldsm4(ah[mt], bA + (uint32_t)(aRow + mt * 16) * 80 + aOff);
                    ldsm4(al[mt], bA + A_PL_B + (uint32_t)(aRow + mt * 16) * 80 + aOff);
                }
#pragma unroll
                for (int bg = 0; bg < 2; bg++) {
                    ldsm4(bh[bg], sb + SM_W + (uint32_t)(bRow + bg * 16) * W_ROW_B + kW);
                    ldsm4(bl[bg], sb + SM_W + W_PLANE_B
                                   + (uint32_t)(bRow + bg * 16) * W_ROW_B + kW);
                }
#pragma unroll
                for (int mt = 0; mt < 4; mt++)
#pragma unroll
                    for (int nt = 0; nt < 4; nt++) {
                        const int g = nt >> 1, s = (nt & 1) * 2;
                        mma16816(acc[mt][nt], ah[mt], bh[g][s], bh[g][s + 1]);
                    }
#pragma unroll
                for (int mt = 0; mt < 4; mt++)
#pragma unroll
                    for (int nt = 0; nt < 4; nt++) {
                        const int g = nt >> 1, s = (nt & 1) * 2;
                        mma16816(acc[mt][nt], ah[mt], bl[g][s], bl[g][s + 1]);
                    }
#pragma unroll
                for (int mt = 0; mt < 4; mt++)
#pragma unroll
                    for (int nt = 0; nt < 4; nt++) {
                        const int g = nt >> 1, s = (nt & 1) * 2;
                        mma16816(acc[mt][nt], al[mt], bh[g][s], bh[g][s + 1]);
                    }
            }
            __syncthreads();
        }

        // ---- epilogue ----
        __half* SHI = (__half*)(smem + SHI_OFF);
        __half* SLO = (__half*)(smem + SLO_OFF);
        const float* projT = g_projP[mode];
#pragma unroll
        for (int mt = 0; mt < 4; mt++) {
#pragma unroll
            for (int nt = 0; nt < 4; nt++) {
                const int ul = myUlB + nt * 2;
                const float4 p = *(const float4*)&projT[(size_t)tokr[mt] * GDIM
                                                        + n0 + ul * 4];
                float c0 = acc[mt][nt][0], c1 = acc[mt][nt][1];
                float c2 = acc[mt][nt][2], c3 = acc[mt][nt][3];
                float sA = odd ? c0 : c2;
                float sB = odd ? c1 : c3;
                float rA = __shfl_xor_sync(0xffffffffu, sA, 1);
                float rB = __shfl_xor_sync(0xffffffffu, sB, 1);
                float gi = odd ? rA : c0;
                float gf = odd ? rB : c1;
                float gg = odd ? c2 : rA;
                float go = odd ? c3 : rB;
                float iv = fast_sigmoid(gi + p.x);
                float fv = fast_sigmoid(gf + p.y);
                float gv = fast_tanh(gg + p.z);
                float ov = fast_sigmoid(go + p.w);
                float cn = fv * cpre[mt][nt] + iv * gv;
                cpre[mt][nt] = cn;
                float hv = ov * fast_tanh(cn);
                __half hi = __float2half_rn(hv);
                __half lo = __float2half_rn(hv - __half2float(hi));
                const int lr = myRow + mt * 16;
                SHI[lr * 34 + ul] = hi;
                SLO[lr * 34 + ul] = lo;
            }
        }
        __syncthreads();

        __half* oHi = g_hs[outPar][0];
        __half* oLo = g_hs[outPar][1];
        const int* SLEN = (const int*)(smem + SM_TOK);
#pragma unroll
        for (int i = 0; i < 16; i++) {
            int f = tid + i * 256;
            int lm = f >> 5, jl = f & 31;
            size_t gidx = (size_t)(m0 + lm) * HDIM + j0g + jl;
            __half hi = SHI[lm * 34 + jl];
            __half lo = SLO[lm * 34 + jl];
            oHi[gidx] = hi;
            oLo[gidx] = lo;
            if (!mode && t == SLEN[lm] - 1) {
                g_eL[0][gidx] = hi;
                g_eL[1][gidx] = lo;
            }
        }
        grid_sync(sense);

        // ================= fc: V-sliced, resident fcW =================
        if (mode) {
            const __half* hH = g_hs[outPar][0];
            const __half* hL = g_hs[outPar][1];
            const int wm2 = wid & 1, wn2 = wid >> 1;
            const int aRowF = wm2 * 64 + (lane & 15);
            const int fbRow = wn2 * 8 + (lane & 7);
            const int fbColH = ((lane >> 3) & 1) * 8;

            float accF[4][4];
#pragma unroll
            for (int i = 0; i < 4; i++)
#pragma unroll
                for (int j = 0; j < 4; j++) accF[i][j] = 0.f;

            load_chunk(sb + SM_STG, hH, hL, m0, 0, tid); cpa_commit();
            load_chunk(sb + SM_STG + A_CH_B, hH, hL, m0, 1, tid); cpa_commit();

            for (int kb = 0; kb < 8; kb++) {
                if (kb < 7) cpa_wait<1>(); else cpa_wait<0>();
                __syncthreads();
                if (kb < 6) {
                    load_chunk(sb + SM_STG + ((kb + 2) % 3) * A_CH_B, hH, hL, m0, kb + 2, tid);
                    cpa_commit();
                }
                const uint32_t bA = sb + SM_STG + (kb % 3) * A_CH_B;
#pragma unroll
                for (int k16 = 0; k16 < 2; k16++) {
                    const uint32_t aOff = (uint32_t)(k16 * 16 + aCol) * 2;
                    const uint32_t kF = (uint32_t)(kb * 32 + k16 * 16 + fbColH) * 2;
                    uint32_t fa_h[4][4], fa_l[4][4], fb_h[2], fb_l[2];
#pragma unroll
                    for (int mt = 0; mt < 4; mt++) {
                        ldsm4(fa_h[mt], bA + (uint32_t)(aRowF + mt * 16) * 80 + aOff);
                        ldsm4(fa_l[mt], bA + A_PL_B + (uint32_t)(aRowF + mt * 16) * 80 + aOff);
                    }
                    ldsm2(fb_h, sb + SM_FCW + (uint32_t)fbRow * W_ROW_B + kF);
                    ldsm2(fb_l, sb + SM_FCW + FCW_PL_B + (uint32_t)fbRow * W_ROW_B + kF);
#pragma unroll
                    for (int mt = 0; mt < 4; mt++) {
                        mma16816(accF[mt], fa_h[mt], fb_h[0], fb_h[1]);
                        mma16816(accF[mt], fa_h[mt], fb_l[0], fb_l[1]);
                        mma16816(accF[mt], fa_l[mt], fb_h[0], fb_h[1]);
                    }
                }
                __syncthreads();
            }

            // stage scores: rows 128, cols 8 per warp-n-group (total 32)
            float* SSC = (float*)(smem + SSC_OFF);
#pragma unroll
            for (int mt = 0; mt < 4; mt++) {
                int r = wm2 * 64 + mt * 16 + (lane >> 2);
                int c = wn2 * 8 + (lane & 3) * 2;
                SSC[r * 33 + c]       = accF[mt][0];
                SSC[r * 33 + c + 1]   = accF[mt][1];
                SSC[(r + 8) * 33 + c]     = accF[mt][2];
                SSC[(r + 8) * 33 + c + 1] = accF[mt][3];
            }
            __syncthreads();

            // bias + out + per-slice argmax; each warp handles 16 rows
            const float* SBIA = (const float*)(smem + SM_BIAS);
            const float myb = SBIA[lane];
#pragma unroll
            for (int rr = 0; rr < 16; rr++) {
                const int r = wid * 16 + rr;
                const int m = m0 + r;
                float s = SSC[r * 33 + lane] + myb;
                out[(size_t)m * (TPH * VOC) + (size_t)(t - TPH) * VOC + bn * 32 + lane] = s;
                float bv = s;
                int   bi = lane;
#pragma unroll
                for (int off = 16; off > 0; off >>= 1) {
                    float ov = __shfl_xor_sync(0xffffffffu, bv, off);
                    int   oi = __shfl_xor_sync(0xffffffffu, bi, off);
                    if (ov > bv || (ov == bv && oi < bi)) { bv = ov; bi = oi; }
                }
                if (lane == 0) {
                    g_pval[bn][m] = bv;
                    g_pidx[bn][m] = bn * 32 + bi;
                }
            }
            grid_sync(sense);
        }
    }
}

// ---------------- launch ----------------
extern "C" void kernel_launch(void* const* d_in, const int* in_sizes, int n_in,
                              void* d_out, int out_size)
{
    const int*   phon   = (const int*)  d_in[0];
    const int*   plen   = (const int*)  d_in[1];
    const float* emb    = (const float*)d_in[2];
    const float* encWih = (const float*)d_in[3];
    const float* encWhh = (const float*)d_in[4];
    const float* encBih = (const float*)d_in[5];
    const float* encBhh = (const float*)d_in[6];
    const float* decWih = (const float*)d_in[7];
    const float* decWhh = (const float*)d_in[8];
    const float* decBih = (const float*)d_in[9];
    const float* decBhh = (const float*)d_in[10];
    const float* fcW    = (const float*)d_in[11];
    const float* fcb    = (const float*)d_in[12];
    const int*   sos    = (const int*)  d_in[13];
    float* out = (float*)d_out;

    cudaFuncSetAttribute(persist_kernel,
                         cudaFuncAttributeMaxDynamicSharedMemorySize, SM_TOTAL);

    prep_kernel<<<6400, 256>>>(encWhh, decWhh, fcW, emb,
                               encWih, encBih, encBhh,
                               decWih, decBih, decBhh);

    persist_kernel<<<NCTA, 256, SM_TOTAL>>>(phon, plen, fcb, sos, out);
}